// round 10
// baseline (speedup 1.0000x reference)
#include <cuda_runtime.h>
#include <math.h>
#include <stdint.h>

#define Bc 512
#define Mc 4096
#define Nc 64
#define Hc 8

// Scratch (device globals, allocation-free rule)
__device__ float g_y[(size_t)Bc * Mc];              // 8 MB, LN'd features (tf32, affine)

__device__ __forceinline__ float tf32r(float x) {
    float r; asm("cvt.rna.tf32.f32 %0, %1;" : "=f"(r) : "f"(x)); return r;
}
__device__ __forceinline__ void mma16n8k8(float* c, const uint32_t* a, const uint32_t* b) {
    asm volatile(
        "mma.sync.aligned.m16n8k8.row.col.f32.tf32.tf32.f32 "
        "{%0,%1,%2,%3}, {%4,%5,%6,%7}, {%8,%9}, {%0,%1,%2,%3};"
        : "+f"(c[0]), "+f"(c[1]), "+f"(c[2]), "+f"(c[3])
        : "r"(a[0]), "r"(a[1]), "r"(a[2]), "r"(a[3]), "r"(b[0]), "r"(b[1]));
}
__device__ __forceinline__ uint32_t smem_u32(const void* p) {
    uint32_t a;
    asm("{ .reg .u64 t; cvta.to.shared.u64 t, %1; cvt.u32.u64 %0, t; }" : "=r"(a) : "l"(p));
    return a;
}
__device__ __forceinline__ void cp16(uint32_t s, const void* g) {
    asm volatile("cp.async.cg.shared.global [%0], [%1], 16;" :: "r"(s), "l"(g));
}
__device__ __forceinline__ void redg_add(float* g, float v) {
    asm volatile("red.global.add.f32 [%0], %1;" :: "l"(g), "f"(v) : "memory");
}
#define CP_COMMIT()  asm volatile("cp.async.commit_group;" ::: "memory")
#define CP_WAIT(n)   asm volatile("cp.async.wait_group %0;" :: "n"(n) : "memory")

// ---------------------------------------------------------------------------
// Kernel 0: LayerNorm -> g_y (tf32, affine) AND zero out[b*4096..] region.
// grid=B, 256 thr.
// ---------------------------------------------------------------------------
static constexpr int SMEMY = 4096 * 4 + 80;

__global__ __launch_bounds__(256) void ln_y_kernel(
    const float* __restrict__ feat, const float* __restrict__ gamma,
    const float* __restrict__ beta, float* __restrict__ out)
{
    extern __shared__ float sm[];
    float* s_x = sm;             // 4096
    float* s_red = sm + 4096;    // 18

    const int b = blockIdx.x, tid = threadIdx.x;
    const int wid = tid >> 5, lane = tid & 31;
    const float4* x4 = (const float4*)(feat + (size_t)b * Mc);

    // zero this batch's out row (poisoned 0xAA by harness; head REDG-accumulates)
    {
        float4* o4 = (float4*)(out + (size_t)b * 4096);
        #pragma unroll
        for (int j = 0; j < 4; j++)
            o4[tid + j * 256] = make_float4(0.f, 0.f, 0.f, 0.f);
    }

    float sum = 0.f, sq = 0.f;
    for (int i = tid; i < 1024; i += 256) {
        float4 v = x4[i];
        *(float4*)&s_x[i * 4] = v;
        sum += v.x + v.y + v.z + v.w;
        sq  += v.x*v.x + v.y*v.y + v.z*v.z + v.w*v.w;
    }
    #pragma unroll
    for (int o = 16; o; o >>= 1) {
        sum += __shfl_xor_sync(~0u, sum, o);
        sq  += __shfl_xor_sync(~0u, sq,  o);
    }
    if (lane == 0) { s_red[wid] = sum; s_red[wid + 8] = sq; }
    __syncthreads();
    if (tid == 0) {
        float S = 0.f, Q = 0.f;
        #pragma unroll
        for (int i = 0; i < 8; i++) { S += s_red[i]; Q += s_red[i + 8]; }
        float mu = S * (1.f / Mc);
        s_red[16] = mu;
        s_red[17] = rsqrtf(Q * (1.f / Mc) - mu * mu + 1e-5f);
    }
    __syncthreads();
    const float mu = s_red[16], rstd = s_red[17];
    float4* y4 = (float4*)(g_y + (size_t)b * Mc);
    const float4* g4 = (const float4*)gamma;
    const float4* b4 = (const float4*)beta;
    for (int i = tid; i < 1024; i += 256) {
        float4 v = *(float4*)&s_x[i * 4];
        float4 g = g4[i], bb = b4[i], y;
        y.x = tf32r((v.x - mu) * rstd * g.x + bb.x);
        y.y = tf32r((v.y - mu) * rstd * g.y + bb.y);
        y.z = tf32r((v.z - mu) * rstd * g.z + bb.z);
        y.w = tf32r((v.w - mu) * rstd * g.w + bb.w);
        y4[i] = y;
    }
}

// ---------------------------------------------------------------------------
// Kernel 1: per-(b,h) head with fused q-proj + FC partial (REDG to out).
// Weights (Wq/Wk/Wfc) are loaded as fragments DIRECTLY from global (L1-resident
// across CTAs — 256 KB total weights < 228 KB... Wk+Wq 128 KB hot per launch).
// smem (floats):
//   @0     kf[64][68] (4352) — gathered feats; S overlay (P3+); hout overlay
//   @4352  feat[4096]        — raw feats; vT[64][68] overlay in phase B
//   @8704  y[64][68] (4352)  — dies after q GEMM; then keyT[64][36]@8704
//                               + q[64][36]@11008 (ends 13312)
//   @13312 wv[16]
// total 13328 floats = 53.3 KB -> 4 CTA/SM.
// ---------------------------------------------------------------------------
static constexpr int SMEM2 = 13328 * 4;

__global__ __launch_bounds__(256, 4) void head_mma(
    const float* __restrict__ feat, const int* __restrict__ sidx,
    const float* __restrict__ Wk, const float* __restrict__ Wv1,
    const float* __restrict__ Wv2, const float* __restrict__ Wq,
    const float* __restrict__ Wfc,
    float* __restrict__ out, float* __restrict__ attn_out)
{
    extern __shared__ float sm[];
    float* s_kf   = sm;            // [64][68]
    float* s_S    = sm;            // overlay
    float* s_vT   = sm + 4352;     // [p][n] pitch 68
    float* s_feat = sm + 4352;
    float* s_y    = sm + 8704;     // dies after q GEMM
    float* s_keyT = sm + 8704;     // [n][d] pitch 36
    float* s_q    = sm + 11008;    // [q][d] pitch 36
    float* s_wv   = sm + 13312;    // wv1[12], wv2[4]

    const int h = blockIdx.x, b = blockIdx.y, tid = threadIdx.x;
    const int wid = tid >> 5, lane = tid & 31;
    const int lr = lane >> 2, lc = lane & 3;
    const int* idx = sidx + (size_t)h * Mc;
    const uint32_t sbase = smem_u32(sm);

    // ---- async staging: G1 = {y}, G2 = {feat} ----
    {
        const float* yg = g_y + (size_t)b * Mc;
        #pragma unroll
        for (int j = 0; j < 4; j++) {
            int i = tid + j * 256;               // 0..1023
            int n = i >> 4, k4 = i & 15;
            cp16(sbase + (uint32_t)(8704 + n * 68 + k4 * 4) * 4, yg + i * 4);
        }
        CP_COMMIT();
        const float* xg = feat + (size_t)b * Mc;
        #pragma unroll
        for (int j = 0; j < 4; j++) {
            int i = tid + j * 256;
            cp16(sbase + (uint32_t)(4352 + i * 4) * 4, xg + i * 4);
        }
        CP_COMMIT();
        if (tid < 12) s_wv[tid] = Wv1[h * 12 + tid];
        if (tid >= 32 && tid < 36) s_wv[12 + tid - 32] = Wv2[h * 4 + tid - 32];
    }

    // ---- phase A1: wait y, q GEMM into registers (feat still in flight).
    //      b-fragments straight from global Wq (L1/L2-resident). ----
    CP_WAIT(1);
    __syncthreads();

    float qacc[2][4] = {};
    const int qm = (wid & 3) * 16;
    const int qd = (wid >> 2) * 16;
    {
        const float* wqh = Wq + (size_t)h * 32 * 64;
        #pragma unroll
        for (int k8 = 0; k8 < 8; k8++) {
            const int k0 = k8 * 8;
            uint32_t a[4];
            a[0] = __float_as_uint(s_y[(qm + lr)     * 68 + k0 + lc]);
            a[1] = __float_as_uint(s_y[(qm + lr + 8) * 68 + k0 + lc]);
            a[2] = __float_as_uint(s_y[(qm + lr)     * 68 + k0 + lc + 4]);
            a[3] = __float_as_uint(s_y[(qm + lr + 8) * 68 + k0 + lc + 4]);
            #pragma unroll
            for (int t = 0; t < 2; t++) {
                const float* wr = wqh + (qd + t * 8 + lr) * 64 + k0 + lc;
                uint32_t bfr[2];
                bfr[0] = __float_as_uint(tf32r(wr[0]));
                bfr[1] = __float_as_uint(tf32r(wr[4]));
                mma16n8k8(qacc[t], a, bfr);
            }
        }
    }

    // ---- phase A2: wait feat, gather kf, conv pad ----
    CP_WAIT(0);
    __syncthreads();
    {
        const int4* idx4 = (const int4*)idx;
        #pragma unroll
        for (int j = 0; j < 4; j++) {
            int i = tid + j * 256;               // 0..1023
            int4 v = idx4[i];
            int n = i >> 4, k = (i & 15) * 4;
            float4 g = make_float4(s_feat[v.x], s_feat[v.y], s_feat[v.z], s_feat[v.w]);
            *(float4*)&s_kf[n * 68 + k] = g;
        }
        if (tid < 128) s_kf[(tid >> 1) * 68 + 64 + (tid & 1)] = 0.f;
    }
    __syncthreads();   // y reads done (A1) -> q/keyT writes now safe

    // ---- phase B: q frag store (x 1/64), key GEMM (Wk a-frags from global), conv
    {
        #pragma unroll
        for (int t = 0; t < 2; t++) {
            const int d = qd + t * 8 + lc * 2;
            s_q[(qm + lr) * 36 + d]         = tf32r(qacc[t][0] * 0.015625f);
            s_q[(qm + lr) * 36 + d + 1]     = tf32r(qacc[t][1] * 0.015625f);
            s_q[(qm + lr + 8) * 36 + d]     = tf32r(qacc[t][2] * 0.015625f);
            s_q[(qm + lr + 8) * 36 + d + 1] = tf32r(qacc[t][3] * 0.015625f);
        }
    }
    {
        const int m0 = (wid & 1) * 16;        // d tile
        const int nb = (wid >> 1) * 8;        // n tiles {nb, nb+32}
        const float* wkh = Wk + (size_t)h * 2048;
        float acc[2][4] = {};
        #pragma unroll
        for (int k8 = 0; k8 < 8; k8++) {
            const int k0 = k8 * 8;
            const float* wr = wkh + (m0 + lr) * 64 + k0 + lc;
            uint32_t a[4];
            a[0] = __float_as_uint(tf32r(wr[0]));
            a[1] = __float_as_uint(tf32r(wr[8 * 64]));
            a[2] = __float_as_uint(tf32r(wr[4]));
            a[3] = __float_as_uint(tf32r(wr[8 * 64 + 4]));
            #pragma unroll
            for (int t = 0; t < 2; t++) {
                const int nn = nb + t * 32;
                uint32_t bfr[2];
                bfr[0] = __float_as_uint(tf32r(s_kf[(nn + lr) * 68 + k0 + lc]));
                bfr[1] = __float_as_uint(tf32r(s_kf[(nn + lr) * 68 + k0 + lc + 4]));
                mma16n8k8(acc[t], a, bfr);
            }
        }
        #pragma unroll
        for (int t = 0; t < 2; t++) {
            const int n = nb + t * 32 + lc * 2, d = m0 + lr;
            s_keyT[n * 36 + d]           = tf32r(acc[t][0]);
            s_keyT[(n + 1) * 36 + d]     = tf32r(acc[t][1]);
            s_keyT[n * 36 + d + 8]       = tf32r(acc[t][2]);
            s_keyT[(n + 1) * 36 + d + 8] = tf32r(acc[t][3]);
        }
    }
    {
        const int n = tid >> 2, p0 = (tid & 3) * 16;
        const float* kr = s_kf + n * 68;
        float w0[4], w1[4], w2[4], w3[4];
        #pragma unroll
        for (int d = 0; d < 4; d++) {
            w0[d] = s_wv[d * 3]; w1[d] = s_wv[d * 3 + 1];
            w2[d] = s_wv[d * 3 + 2]; w3[d] = s_wv[12 + d];
        }
        float x0 = kr[p0], x1 = kr[p0 + 1];
        #pragma unroll
        for (int i = 0; i < 16; i++) {
            float x2 = kr[p0 + i + 2];
            float acc = x0;
            #pragma unroll
            for (int d = 0; d < 4; d++)
                acc += fmaxf(x0 * w0[d] + x1 * w1[d] + x2 * w2[d], 0.f) * w3[d];
            s_vT[(p0 + i) * 68 + n] = tf32r(acc);
            x0 = x1; x1 = x2;
        }
    }
    __syncthreads();

    const int m0 = (wid >> 1) * 16;       // q tile
    const int nb4 = (wid & 1) * 4;        // 4 n-tiles

    // ---- P3: S[q][n] = sum_d q[q][d] * keyT[n][d] -> S overlay (kf dead) ----
    {
        float acc[4][4] = {};
        #pragma unroll
        for (int k8 = 0; k8 < 4; k8++) {
            const int k0 = k8 * 8;
            uint32_t a[4];
            a[0] = __float_as_uint(s_q[(m0 + lr)     * 36 + k0 + lc]);
            a[1] = __float_as_uint(s_q[(m0 + lr + 8) * 36 + k0 + lc]);
            a[2] = __float_as_uint(s_q[(m0 + lr)     * 36 + k0 + lc + 4]);
            a[3] = __float_as_uint(s_q[(m0 + lr + 8) * 36 + k0 + lc + 4]);
            #pragma unroll
            for (int j = 0; j < 4; j++) {
                const int nn = (nb4 + j) * 8;
                uint32_t bfr[2];
                bfr[0] = __float_as_uint(s_keyT[(nn + lr) * 36 + k0 + lc]);
                bfr[1] = __float_as_uint(s_keyT[(nn + lr) * 36 + k0 + lc + 4]);
                mma16n8k8(acc[j], a, bfr);
            }
        }
        #pragma unroll
        for (int j = 0; j < 4; j++) {
            const int col = (nb4 + j) * 8 + lc * 2;
            *(float2*)&s_S[(m0 + lr)     * 68 + col] = make_float2(acc[j][0], acc[j][1]);
            *(float2*)&s_S[(m0 + lr + 8) * 68 + col] = make_float2(acc[j][2], acc[j][3]);
        }
    }
    __syncthreads();

    // ---- P4: softmax rows of S; global attn fp32, smem tf32 ----
    {
        const int r = tid >> 2, s3 = tid & 3;
        float* row = s_S + r * 68 + s3 * 16;
        float4 v0 = *(float4*)&row[0], v1 = *(float4*)&row[4];
        float4 v2 = *(float4*)&row[8], v3 = *(float4*)&row[12];
        float mx = fmaxf(fmaxf(fmaxf(v0.x, v0.y), fmaxf(v0.z, v0.w)),
                         fmaxf(fmaxf(v1.x, v1.y), fmaxf(v1.z, v1.w)));
        mx = fmaxf(mx, fmaxf(fmaxf(fmaxf(v2.x, v2.y), fmaxf(v2.z, v2.w)),
                             fmaxf(fmaxf(v3.x, v3.y), fmaxf(v3.z, v3.w))));
        mx = fmaxf(mx, __shfl_xor_sync(~0u, mx, 1));
        mx = fmaxf(mx, __shfl_xor_sync(~0u, mx, 2));
        float e[16];
        e[0]=__expf(v0.x-mx); e[1]=__expf(v0.y-mx); e[2]=__expf(v0.z-mx); e[3]=__expf(v0.w-mx);
        e[4]=__expf(v1.x-mx); e[5]=__expf(v1.y-mx); e[6]=__expf(v1.z-mx); e[7]=__expf(v1.w-mx);
        e[8]=__expf(v2.x-mx); e[9]=__expf(v2.y-mx); e[10]=__expf(v2.z-mx); e[11]=__expf(v2.w-mx);
        e[12]=__expf(v3.x-mx); e[13]=__expf(v3.y-mx); e[14]=__expf(v3.z-mx); e[15]=__expf(v3.w-mx);
        float ssum = 0.f;
        #pragma unroll
        for (int i = 0; i < 16; i++) ssum += e[i];
        ssum += __shfl_xor_sync(~0u, ssum, 1);
        ssum += __shfl_xor_sync(~0u, ssum, 2);
        const float inv = 1.f / ssum;
        float* gattn = attn_out + (((size_t)(b * Hc + h) * Nc + r) * Nc) + s3 * 16;
        #pragma unroll
        for (int u = 0; u < 4; u++) {
            float p0 = e[4*u] * inv, p1 = e[4*u+1] * inv,
                  p2 = e[4*u+2] * inv, p3 = e[4*u+3] * inv;
            *(float4*)&gattn[4 * u] = make_float4(p0, p1, p2, p3);
            *(float4*)&row[4 * u]   = make_float4(tf32r(p0), tf32r(p1), tf32r(p2), tf32r(p3));
        }
    }
    __syncthreads();

    // ---- P5: hout[q][p] = sum_n attn[q][n] * vT[p][n] (registers) ----
    float hacc[4][4] = {};
    {
        #pragma unroll
        for (int k8 = 0; k8 < 8; k8++) {
            const int k0 = k8 * 8;
            uint32_t a[4];
            a[0] = __float_as_uint(s_S[(m0 + lr)     * 68 + k0 + lc]);
            a[1] = __float_as_uint(s_S[(m0 + lr + 8) * 68 + k0 + lc]);
            a[2] = __float_as_uint(s_S[(m0 + lr)     * 68 + k0 + lc + 4]);
            a[3] = __float_as_uint(s_S[(m0 + lr + 8) * 68 + k0 + lc + 4]);
            #pragma unroll
            for (int j = 0; j < 4; j++) {
                const int pp = (nb4 + j) * 8;
                uint32_t bfr[2];
                bfr[0] = __float_as_uint(s_vT[(pp + lr) * 68 + k0 + lc]);
                bfr[1] = __float_as_uint(s_vT[(pp + lr) * 68 + k0 + lc + 4]);
                mma16n8k8(hacc[j], a, bfr);
            }
        }
    }
    __syncthreads();   // all P5 reads of S done -> hout overlay safe

    // ---- store hout (tf32) into S region ----
    {
        #pragma unroll
        for (int j = 0; j < 4; j++) {
            const int p = (nb4 + j) * 8 + lc * 2;
            *(float2*)&s_S[(m0 + lr) * 68 + p] =
                make_float2(tf32r(hacc[j][0]), tf32r(hacc[j][1]));
            *(float2*)&s_S[(m0 + lr + 8) * 68 + p] =
                make_float2(tf32r(hacc[j][2]), tf32r(hacc[j][3]));
        }
    }
    __syncthreads();

    // ---- P6: FC partial  po[n][o] = sum_p hout[n][p] * Wfc[o][h*64+p]; REDG ----
    {
        const int fm = (wid >> 1) * 16;      // n rows
        const int fo = (wid & 1) * 32;       // o cols (4 n8-tiles)
        const float* wfh = Wfc + h * 64;
        float acc[4][4] = {};
        #pragma unroll
        for (int k8 = 0; k8 < 8; k8++) {
            const int k0 = k8 * 8;
            uint32_t a[4];
            a[0] = __float_as_uint(s_S[(fm + lr)     * 68 + k0 + lc]);
            a[1] = __float_as_uint(s_S[(fm + lr + 8) * 68 + k0 + lc]);
            a[2] = __float_as_uint(s_S[(fm + lr)     * 68 + k0 + lc + 4]);
            a[3] = __float_as_uint(s_S[(fm + lr + 8) * 68 + k0 + lc + 4]);
            #pragma unroll
            for (int t = 0; t < 4; t++) {
                const float* wr = wfh + (size_t)(fo + t * 8 + lr) * 512 + k0 + lc;
                uint32_t bfr[2];
                bfr[0] = __float_as_uint(tf32r(wr[0]));
                bfr[1] = __float_as_uint(tf32r(wr[4]));
                mma16n8k8(acc[t], a, bfr);
            }
        }
        float* ob = out + (size_t)b * 4096;
        #pragma unroll
        for (int t = 0; t < 4; t++) {
            const int o = fo + t * 8 + lc * 2;
            redg_add(ob + (fm + lr) * 64 + o,     acc[t][0]);
            redg_add(ob + (fm + lr) * 64 + o + 1, acc[t][1]);
            redg_add(ob + (fm + lr + 8) * 64 + o,     acc[t][2]);
            redg_add(ob + (fm + lr + 8) * 64 + o + 1, acc[t][3]);
        }
    }
}

// ---------------------------------------------------------------------------
extern "C" void kernel_launch(void* const* d_in, const int* in_sizes, int n_in,
                              void* d_out, int out_size) {
    const float* feat  = (const float*)d_in[0];
    const int*   sidx  = (const int*)  d_in[1];
    const float* gamma = (const float*)d_in[2];
    const float* beta  = (const float*)d_in[3];
    const float* Wq    = (const float*)d_in[4];
    const float* Wk    = (const float*)d_in[5];
    const float* Wv1   = (const float*)d_in[6];
    const float* Wv2   = (const float*)d_in[7];
    const float* Wfc   = (const float*)d_in[8];

    float* out  = (float*)d_out;
    float* attn = out + (size_t)Bc * Nc * 64;

    cudaFuncSetAttribute(ln_y_kernel, cudaFuncAttributeMaxDynamicSharedMemorySize, SMEMY);
    cudaFuncSetAttribute(head_mma,    cudaFuncAttributeMaxDynamicSharedMemorySize, SMEM2);

    ln_y_kernel<<<Bc, 256, SMEMY>>>(feat, gamma, beta, out);
    head_mma<<<dim3(Hc, Bc), 256, SMEM2>>>(feat, sidx, Wk, Wv1, Wv2, Wq, Wfc, out, attn);
}

// round 11
// speedup vs baseline: 1.5666x; 1.5666x over previous
#include <cuda_runtime.h>
#include <math.h>
#include <stdint.h>

#define Bc 512
#define Mc 4096
#define Nc 64
#define Hc 8

// Scratch (device globals, allocation-free rule)
__device__ float g_y[(size_t)Bc * Mc];              // 8 MB, LN'd features (tf32, affine)

__device__ __forceinline__ float tf32r(float x) {
    float r; asm("cvt.rna.tf32.f32 %0, %1;" : "=f"(r) : "f"(x)); return r;
}
__device__ __forceinline__ void mma16n8k8(float* c, const uint32_t* a, const uint32_t* b) {
    asm volatile(
        "mma.sync.aligned.m16n8k8.row.col.f32.tf32.tf32.f32 "
        "{%0,%1,%2,%3}, {%4,%5,%6,%7}, {%8,%9}, {%0,%1,%2,%3};"
        : "+f"(c[0]), "+f"(c[1]), "+f"(c[2]), "+f"(c[3])
        : "r"(a[0]), "r"(a[1]), "r"(a[2]), "r"(a[3]), "r"(b[0]), "r"(b[1]));
}
__device__ __forceinline__ uint32_t smem_u32(const void* p) {
    uint32_t a;
    asm("{ .reg .u64 t; cvta.to.shared.u64 t, %1; cvt.u32.u64 %0, t; }" : "=r"(a) : "l"(p));
    return a;
}
__device__ __forceinline__ void cp16(uint32_t s, const void* g) {
    asm volatile("cp.async.cg.shared.global [%0], [%1], 16;" :: "r"(s), "l"(g));
}
__device__ __forceinline__ void redg_add(float* g, float v) {
    asm volatile("red.global.add.f32 [%0], %1;" :: "l"(g), "f"(v) : "memory");
}
#define CP_COMMIT()  asm volatile("cp.async.commit_group;" ::: "memory")
#define CP_WAIT(n)   asm volatile("cp.async.wait_group %0;" :: "n"(n) : "memory")

// ---------------------------------------------------------------------------
// Kernel 0: LayerNorm -> g_y (tf32, affine) AND zero out[b] row. grid=B.
// ---------------------------------------------------------------------------
static constexpr int SMEMY = 4096 * 4 + 80;

__global__ __launch_bounds__(256) void ln_y_kernel(
    const float* __restrict__ feat, const float* __restrict__ gamma,
    const float* __restrict__ beta, float* __restrict__ out)
{
    extern __shared__ float sm[];
    float* s_x = sm;
    float* s_red = sm + 4096;

    const int b = blockIdx.x, tid = threadIdx.x;
    const int wid = tid >> 5, lane = tid & 31;
    const float4* x4 = (const float4*)(feat + (size_t)b * Mc);

    {
        float4* o4 = (float4*)(out + (size_t)b * 4096);
        #pragma unroll
        for (int j = 0; j < 4; j++)
            o4[tid + j * 256] = make_float4(0.f, 0.f, 0.f, 0.f);
    }

    float sum = 0.f, sq = 0.f;
    for (int i = tid; i < 1024; i += 256) {
        float4 v = x4[i];
        *(float4*)&s_x[i * 4] = v;
        sum += v.x + v.y + v.z + v.w;
        sq  += v.x*v.x + v.y*v.y + v.z*v.z + v.w*v.w;
    }
    #pragma unroll
    for (int o = 16; o; o >>= 1) {
        sum += __shfl_xor_sync(~0u, sum, o);
        sq  += __shfl_xor_sync(~0u, sq,  o);
    }
    if (lane == 0) { s_red[wid] = sum; s_red[wid + 8] = sq; }
    __syncthreads();
    if (tid == 0) {
        float S = 0.f, Q = 0.f;
        #pragma unroll
        for (int i = 0; i < 8; i++) { S += s_red[i]; Q += s_red[i + 8]; }
        float mu = S * (1.f / Mc);
        s_red[16] = mu;
        s_red[17] = rsqrtf(Q * (1.f / Mc) - mu * mu + 1e-5f);
    }
    __syncthreads();
    const float mu = s_red[16], rstd = s_red[17];
    float4* y4 = (float4*)(g_y + (size_t)b * Mc);
    const float4* g4 = (const float4*)gamma;
    const float4* b4 = (const float4*)beta;
    for (int i = tid; i < 1024; i += 256) {
        float4 v = *(float4*)&s_x[i * 4];
        float4 g = g4[i], bb = b4[i], y;
        y.x = tf32r((v.x - mu) * rstd * g.x + bb.x);
        y.y = tf32r((v.y - mu) * rstd * g.y + bb.y);
        y.z = tf32r((v.z - mu) * rstd * g.z + bb.z);
        y.w = tf32r((v.w - mu) * rstd * g.w + bb.w);
        y4[i] = y;
    }
}

// ---------------------------------------------------------------------------
// Kernel 1: (h, 2 batches) per CTA, 512 threads (warps 0-7 bA, 8-15 bB).
// Weights staged once per CTA in smem (R9-proven path); compact transposed
// qT/keyTd layouts keep smem at 113.2 KB -> 2 CTA/SM (32 warps).
// smem map (floats):
//   @0     kfA[64][68]  (S_A overlay)  [wq[32][68] overlay @0 during A1]
//   @4352  kfB[64][68]  (S_B overlay)
//   @8704  featA[4096]  (vT_A[64][68] overlay)
//   @13056 featB[4096]  (vT_B overlay)
//   @17408 yA[64][68] -> keyTd_A[32][68]@17408 + qT_A[32][68]@19584
//                       [wfc[64][68] overlay @17408 after P3]
//   @21760 yB[64][68] -> keyTd_B@21760 + qT_B@23936
//   @26112 wk[32][68]
//   @28288 wv[16]
// total 28304 floats = 113216 B.
// ---------------------------------------------------------------------------
static constexpr int SMEM2 = 28304 * 4;

__global__ __launch_bounds__(512, 2) void head_mma(
    const float* __restrict__ feat, const int* __restrict__ sidx,
    const float* __restrict__ Wk, const float* __restrict__ Wv1,
    const float* __restrict__ Wv2, const float* __restrict__ Wq,
    const float* __restrict__ Wfc,
    float* __restrict__ out, float* __restrict__ attn_out)
{
    extern __shared__ float sm[];
    const int h = blockIdx.x, tid = threadIdx.x;
    const int half = tid >> 8, tid_h = tid & 255;
    const int wl = tid_h >> 5, lane = tid & 31;
    const int lr = lane >> 2, lc = lane & 3;
    const int b = blockIdx.y * 2 + half;
    const int* idx = sidx + (size_t)h * Mc;
    const uint32_t sbase = smem_u32(sm);

    float* s_kf    = sm + half * 4352;            // [64][68]
    float* s_S     = s_kf;                        // overlay
    float* s_feat  = sm + 8704 + half * 4352;
    float* s_vT    = s_feat;                      // [p][n] pitch 68
    float* s_y     = sm + 17408 + half * 4352;    // [n][k] pitch 68
    float* s_keyTd = s_y;                         // [d][n] pitch 68
    float* s_qT    = s_y + 2176;                  // [d][q] pitch 68
    float* s_wq    = sm;                          // @0 during A1 (raw)
    float* s_wfc   = sm + 17408;                  // after P3 (raw)
    float* s_wk    = sm + 26112;                  // raw
    float* s_wv    = sm + 28288;

    const uint32_t off_y   = (17408 + half * 4352) * 4;
    const uint32_t off_ft  = (8704 + half * 4352) * 4;

    // ---- async staging: G1 = {yA, yB, wq}, G2 = {featA, featB, wk} ----
    {
        const float* yg = g_y + (size_t)b * Mc;
        #pragma unroll
        for (int j = 0; j < 4; j++) {
            int i = tid_h + j * 256;             // 0..1023
            int n = i >> 4, k4 = i & 15;
            cp16(sbase + off_y + (uint32_t)(n * 68 + k4 * 4) * 4, yg + i * 4);
        }
        {   // wq: 512 cp16 (whole block)
            int e = tid >> 4, k4 = tid & 15;
            cp16(sbase + (uint32_t)(e * 68 + k4 * 4) * 4,
                 Wq + (size_t)(h * 32 + e) * 64 + k4 * 4);
        }
        CP_COMMIT();
        const float* xg = feat + (size_t)b * Mc;
        #pragma unroll
        for (int j = 0; j < 4; j++) {
            int i = tid_h + j * 256;
            cp16(sbase + off_ft + (uint32_t)(i * 4) * 4, xg + i * 4);
        }
        {   // wk: 512 cp16
            int d = tid >> 4, k4 = tid & 15;
            cp16(sbase + (uint32_t)(26112 + d * 68 + k4 * 4) * 4,
                 Wk + (size_t)(h * 32 + d) * 64 + k4 * 4);
        }
        CP_COMMIT();
        if (tid < 12) s_wv[tid] = Wv1[h * 12 + tid];
        if (tid >= 32 && tid < 36) s_wv[12 + tid - 32] = Wv2[h * 4 + tid - 32];
    }

    // ---- A1: wait y/wq, q GEMM into registers (feat/wk in flight) ----
    CP_WAIT(1);
    __syncthreads();

    float qacc[2][4] = {};
    const int qm = (wl & 3) * 16;
    const int qd = (wl >> 2) * 16;
    {
        #pragma unroll
        for (int k8 = 0; k8 < 8; k8++) {
            const int k0 = k8 * 8;
            uint32_t a[4];
            a[0] = __float_as_uint(s_y[(qm + lr)     * 68 + k0 + lc]);
            a[1] = __float_as_uint(s_y[(qm + lr + 8) * 68 + k0 + lc]);
            a[2] = __float_as_uint(s_y[(qm + lr)     * 68 + k0 + lc + 4]);
            a[3] = __float_as_uint(s_y[(qm + lr + 8) * 68 + k0 + lc + 4]);
            #pragma unroll
            for (int t = 0; t < 2; t++) {
                uint32_t bfr[2];
                bfr[0] = __float_as_uint(tf32r(s_wq[(qd + t * 8 + lr) * 68 + k0 + lc]));
                bfr[1] = __float_as_uint(tf32r(s_wq[(qd + t * 8 + lr) * 68 + k0 + lc + 4]));
                mma16n8k8(qacc[t], a, bfr);
            }
        }
    }

    // ---- A2: wait feat/wk, gather kf (kf/wq region now reusable), conv pad ----
    CP_WAIT(0);
    __syncthreads();
    {
        const int4* idx4 = (const int4*)idx;
        #pragma unroll
        for (int j = 0; j < 4; j++) {
            int i = tid_h + j * 256;             // 0..1023
            int4 v = idx4[i];
            int n = i >> 4, k = (i & 15) * 4;
            float4 g = make_float4(s_feat[v.x], s_feat[v.y], s_feat[v.z], s_feat[v.w]);
            *(float4*)&s_kf[n * 68 + k] = g;
        }
        if (tid_h < 128) s_kf[(tid_h >> 1) * 68 + 64 + (tid_h & 1)] = 0.f;
    }
    __syncthreads();   // y reads done -> qT/keyTd writes safe

    // ---- B: qT store (x 1/64), key GEMM -> keyTd, conv -> vT ----
    {
        #pragma unroll
        for (int t = 0; t < 2; t++) {
            const int d = qd + t * 8 + lc * 2;
            s_qT[d * 68 + qm + lr]           = tf32r(qacc[t][0] * 0.015625f);
            s_qT[(d + 1) * 68 + qm + lr]     = tf32r(qacc[t][1] * 0.015625f);
            s_qT[d * 68 + qm + lr + 8]       = tf32r(qacc[t][2] * 0.015625f);
            s_qT[(d + 1) * 68 + qm + lr + 8] = tf32r(qacc[t][3] * 0.015625f);
        }
    }
    {
        const int m0 = (wl & 1) * 16;         // d tile
        const int nb = (wl >> 1) * 8;         // n tiles {nb, nb+32}
        float acc[2][4] = {};
        #pragma unroll
        for (int k8 = 0; k8 < 8; k8++) {
            const int k0 = k8 * 8;
            uint32_t a[4];
            a[0] = __float_as_uint(tf32r(s_wk[(m0 + lr)     * 68 + k0 + lc]));
            a[1] = __float_as_uint(tf32r(s_wk[(m0 + lr + 8) * 68 + k0 + lc]));
            a[2] = __float_as_uint(tf32r(s_wk[(m0 + lr)     * 68 + k0 + lc + 4]));
            a[3] = __float_as_uint(tf32r(s_wk[(m0 + lr + 8) * 68 + k0 + lc + 4]));
            #pragma unroll
            for (int t = 0; t < 2; t++) {
                const int nn = nb + t * 32;
                uint32_t bfr[2];
                bfr[0] = __float_as_uint(tf32r(s_kf[(nn + lr) * 68 + k0 + lc]));
                bfr[1] = __float_as_uint(tf32r(s_kf[(nn + lr) * 68 + k0 + lc + 4]));
                mma16n8k8(acc[t], a, bfr);
            }
        }
        #pragma unroll
        for (int t = 0; t < 2; t++) {
            const int n = nb + t * 32 + lc * 2;
            s_keyTd[(m0 + lr) * 68 + n]         = tf32r(acc[t][0]);
            s_keyTd[(m0 + lr) * 68 + n + 1]     = tf32r(acc[t][1]);
            s_keyTd[(m0 + lr + 8) * 68 + n]     = tf32r(acc[t][2]);
            s_keyTd[(m0 + lr + 8) * 68 + n + 1] = tf32r(acc[t][3]);
        }
    }
    {
        const int n = tid_h >> 2, p0 = (tid_h & 3) * 16;
        const float* kr = s_kf + n * 68;
        float w0[4], w1[4], w2[4], w3[4];
        #pragma unroll
        for (int d = 0; d < 4; d++) {
            w0[d] = s_wv[d * 3]; w1[d] = s_wv[d * 3 + 1];
            w2[d] = s_wv[d * 3 + 2]; w3[d] = s_wv[12 + d];
        }
        float x0 = kr[p0], x1 = kr[p0 + 1];
        #pragma unroll
        for (int i = 0; i < 16; i++) {
            float x2 = kr[p0 + i + 2];
            float acc = x0;
            #pragma unroll
            for (int d = 0; d < 4; d++)
                acc += fmaxf(x0 * w0[d] + x1 * w1[d] + x2 * w2[d], 0.f) * w3[d];
            s_vT[(p0 + i) * 68 + n] = tf32r(acc);
            x0 = x1; x1 = x2;
        }
    }
    __syncthreads();

    const int m0 = (wl >> 1) * 16;        // q tile
    const int nb4 = (wl & 1) * 4;         // 4 n-tiles

    // ---- P3: S[q][n] = sum_d qT/keyTd (transposed reads) -> S overlay ----
    {
        float acc[4][4] = {};
        #pragma unroll
        for (int k8 = 0; k8 < 4; k8++) {
            const int k0 = k8 * 8;
            uint32_t a[4];
            a[0] = __float_as_uint(s_qT[(k0 + lc) * 68 + m0 + lr]);
            a[1] = __float_as_uint(s_qT[(k0 + lc) * 68 + m0 + lr + 8]);
            a[2] = __float_as_uint(s_qT[(k0 + lc + 4) * 68 + m0 + lr]);
            a[3] = __float_as_uint(s_qT[(k0 + lc + 4) * 68 + m0 + lr + 8]);
            #pragma unroll
            for (int j = 0; j < 4; j++) {
                const int nn = (nb4 + j) * 8;
                uint32_t bfr[2];
                bfr[0] = __float_as_uint(s_keyTd[(k0 + lc) * 68 + nn + lr]);
                bfr[1] = __float_as_uint(s_keyTd[(k0 + lc + 4) * 68 + nn + lr]);
                mma16n8k8(acc[j], a, bfr);
            }
        }
        #pragma unroll
        for (int j = 0; j < 4; j++) {
            const int col = (nb4 + j) * 8 + lc * 2;
            *(float2*)&s_S[(m0 + lr)     * 68 + col] = make_float2(acc[j][0], acc[j][1]);
            *(float2*)&s_S[(m0 + lr + 8) * 68 + col] = make_float2(acc[j][2], acc[j][3]);
        }
    }
    __syncthreads();   // keyTd/qT dead (both halves)

    // ---- stage wfc[o][p-slice] into dead region @17408 (1088 cp16) ----
    for (int i = tid; i < 1088; i += 512) {
        int o = i >> 4, p4 = i & 15;
        cp16(sbase + (uint32_t)(17408 + o * 68 + p4 * 4) * 4,
             Wfc + (size_t)o * 512 + h * 64 + p4 * 4);
    }
    CP_COMMIT();

    // ---- P4: softmax rows of S; global attn fp32, smem tf32 ----
    {
        const int r = tid_h >> 2, s3 = tid_h & 3;
        float* row = s_S + r * 68 + s3 * 16;
        float4 v0 = *(float4*)&row[0], v1 = *(float4*)&row[4];
        float4 v2 = *(float4*)&row[8], v3 = *(float4*)&row[12];
        float mx = fmaxf(fmaxf(fmaxf(v0.x, v0.y), fmaxf(v0.z, v0.w)),
                         fmaxf(fmaxf(v1.x, v1.y), fmaxf(v1.z, v1.w)));
        mx = fmaxf(mx, fmaxf(fmaxf(fmaxf(v2.x, v2.y), fmaxf(v2.z, v2.w)),
                             fmaxf(fmaxf(v3.x, v3.y), fmaxf(v3.z, v3.w))));
        mx = fmaxf(mx, __shfl_xor_sync(~0u, mx, 1));
        mx = fmaxf(mx, __shfl_xor_sync(~0u, mx, 2));
        float e[16];
        e[0]=__expf(v0.x-mx); e[1]=__expf(v0.y-mx); e[2]=__expf(v0.z-mx); e[3]=__expf(v0.w-mx);
        e[4]=__expf(v1.x-mx); e[5]=__expf(v1.y-mx); e[6]=__expf(v1.z-mx); e[7]=__expf(v1.w-mx);
        e[8]=__expf(v2.x-mx); e[9]=__expf(v2.y-mx); e[10]=__expf(v2.z-mx); e[11]=__expf(v2.w-mx);
        e[12]=__expf(v3.x-mx); e[13]=__expf(v3.y-mx); e[14]=__expf(v3.z-mx); e[15]=__expf(v3.w-mx);
        float ssum = 0.f;
        #pragma unroll
        for (int i = 0; i < 16; i++) ssum += e[i];
        ssum += __shfl_xor_sync(~0u, ssum, 1);
        ssum += __shfl_xor_sync(~0u, ssum, 2);
        const float inv = 1.f / ssum;
        float* gattn = attn_out + (((size_t)(b * Hc + h) * Nc + r) * Nc) + s3 * 16;
        #pragma unroll
        for (int u = 0; u < 4; u++) {
            float p0 = e[4*u] * inv, p1 = e[4*u+1] * inv,
                  p2 = e[4*u+2] * inv, p3 = e[4*u+3] * inv;
            *(float4*)&gattn[4 * u] = make_float4(p0, p1, p2, p3);
            *(float4*)&row[4 * u]   = make_float4(tf32r(p0), tf32r(p1), tf32r(p2), tf32r(p3));
        }
    }
    __syncthreads();

    // ---- P5: hout[q][p] = sum_n attn[q][n] * vT[p][n] (registers) ----
    float hacc[4][4] = {};
    {
        #pragma unroll
        for (int k8 = 0; k8 < 8; k8++) {
            const int k0 = k8 * 8;
            uint32_t a[4];
            a[0] = __float_as_uint(s_S[(m0 + lr)     * 68 + k0 + lc]);
            a[1] = __float_as_uint(s_S[(m0 + lr + 8) * 68 + k0 + lc]);
            a[2] = __float_as_uint(s_S[(m0 + lr)     * 68 + k0 + lc + 4]);
            a[3] = __float_as_uint(s_S[(m0 + lr + 8) * 68 + k0 + lc + 4]);
            #pragma unroll
            for (int j = 0; j < 4; j++) {
                const int pp = (nb4 + j) * 8;
                uint32_t bfr[2];
                bfr[0] = __float_as_uint(s_vT[(pp + lr) * 68 + k0 + lc]);
                bfr[1] = __float_as_uint(s_vT[(pp + lr) * 68 + k0 + lc + 4]);
                mma16n8k8(hacc[j], a, bfr);
            }
        }
    }
    __syncthreads();   // S reads done -> hout overlay safe

    // ---- store hout (tf32) into S region ----
    {
        #pragma unroll
        for (int j = 0; j < 4; j++) {
            const int p = (nb4 + j) * 8 + lc * 2;
            *(float2*)&s_S[(m0 + lr) * 68 + p] =
                make_float2(tf32r(hacc[j][0]), tf32r(hacc[j][1]));
            *(float2*)&s_S[(m0 + lr + 8) * 68 + p] =
                make_float2(tf32r(hacc[j][2]), tf32r(hacc[j][3]));
        }
    }
    CP_WAIT(0);        // wfc landed
    __syncthreads();

    // ---- P6: FC partial  po[n][o] = sum_p hout[n][p] * wfc[o][p]; REDG ----
    {
        const int fm = (wl >> 1) * 16;       // n rows
        const int fo = (wl & 1) * 32;        // o cols (4 n8-tiles)
        float acc[4][4] = {};
        #pragma unroll
        for (int k8 = 0; k8 < 8; k8++) {
            const int k0 = k8 * 8;
            uint32_t a[4];
            a[0] = __float_as_uint(s_S[(fm + lr)     * 68 + k0 + lc]);
            a[1] = __float_as_uint(s_S[(fm + lr + 8) * 68 + k0 + lc]);
            a[2] = __float_as_uint(s_S[(fm + lr)     * 68 + k0 + lc + 4]);
            a[3] = __float_as_uint(s_S[(fm + lr + 8) * 68 + k0 + lc + 4]);
            #pragma unroll
            for (int t = 0; t < 4; t++) {
                uint32_t bfr[2];
                bfr[0] = __float_as_uint(tf32r(s_wfc[(fo + t * 8 + lr) * 68 + k0 + lc]));
                bfr[1] = __float_as_uint(tf32r(s_wfc[(fo + t * 8 + lr) * 68 + k0 + lc + 4]));
                mma16n8k8(acc[t], a, bfr);
            }
        }
        float* ob = out + (size_t)b * 4096;
        #pragma unroll
        for (int t = 0; t < 4; t++) {
            const int o = fo + t * 8 + lc * 2;
            redg_add(ob + (fm + lr) * 64 + o,     acc[t][0]);
            redg_add(ob + (fm + lr) * 64 + o + 1, acc[t][1]);
            redg_add(ob + (fm + lr + 8) * 64 + o,     acc[t][2]);
            redg_add(ob + (fm + lr + 8) * 64 + o + 1, acc[t][3]);
        }
    }
}

// ---------------------------------------------------------------------------
extern "C" void kernel_launch(void* const* d_in, const int* in_sizes, int n_in,
                              void* d_out, int out_size) {
    const float* feat  = (const float*)d_in[0];
    const int*   sidx  = (const int*)  d_in[1];
    const float* gamma = (const float*)d_in[2];
    const float* beta  = (const float*)d_in[3];
    const float* Wq    = (const float*)d_in[4];
    const float* Wk    = (const float*)d_in[5];
    const float* Wv1   = (const float*)d_in[6];
    const float* Wv2   = (const float*)d_in[7];
    const float* Wfc   = (const float*)d_in[8];

    float* out  = (float*)d_out;
    float* attn = out + (size_t)Bc * Nc * 64;

    cudaFuncSetAttribute(ln_y_kernel, cudaFuncAttributeMaxDynamicSharedMemorySize, SMEMY);
    cudaFuncSetAttribute(head_mma,    cudaFuncAttributeMaxDynamicSharedMemorySize, SMEM2);

    ln_y_kernel<<<Bc, 256, SMEMY>>>(feat, gamma, beta, out);
    head_mma<<<dim3(Hc, Bc / 2), 512, SMEM2>>>(feat, sidx, Wk, Wv1, Wv2, Wq, Wfc, out, attn);
}

// round 12
// speedup vs baseline: 1.6612x; 1.0604x over previous
#include <cuda_runtime.h>
#include <math.h>
#include <stdint.h>

#define Bc 512
#define Mc 4096
#define Nc 64
#define Hc 8

// Scratch (device globals, allocation-free rule)
__device__ float g_y[(size_t)Bc * Mc];              // 8 MB, LN'd features (tf32, affine)

__device__ __forceinline__ float tf32r(float x) {
    float r; asm("cvt.rna.tf32.f32 %0, %1;" : "=f"(r) : "f"(x)); return r;
}
__device__ __forceinline__ void mma16n8k8(float* c, const uint32_t* a, const uint32_t* b) {
    asm volatile(
        "mma.sync.aligned.m16n8k8.row.col.f32.tf32.tf32.f32 "
        "{%0,%1,%2,%3}, {%4,%5,%6,%7}, {%8,%9}, {%0,%1,%2,%3};"
        : "+f"(c[0]), "+f"(c[1]), "+f"(c[2]), "+f"(c[3])
        : "r"(a[0]), "r"(a[1]), "r"(a[2]), "r"(a[3]), "r"(b[0]), "r"(b[1]));
}
__device__ __forceinline__ uint32_t smem_u32(const void* p) {
    uint32_t a;
    asm("{ .reg .u64 t; cvta.to.shared.u64 t, %1; cvt.u32.u64 %0, t; }" : "=r"(a) : "l"(p));
    return a;
}
__device__ __forceinline__ void cp16(uint32_t s, const void* g) {
    asm volatile("cp.async.cg.shared.global [%0], [%1], 16;" :: "r"(s), "l"(g));
}
__device__ __forceinline__ void redg_add(float* g, float v) {
    asm volatile("red.global.add.f32 [%0], %1;" :: "l"(g), "f"(v) : "memory");
}
#define CP_COMMIT()  asm volatile("cp.async.commit_group;" ::: "memory")
#define CP_WAIT(n)   asm volatile("cp.async.wait_group %0;" :: "n"(n) : "memory")
#define BAR_SYNC(id, cnt) asm volatile("bar.sync %0, %1;" :: "r"(id), "r"(cnt) : "memory")

// ---------------------------------------------------------------------------
// Kernel 0: LayerNorm -> g_y (tf32, affine) AND zero out[b] row. grid=B.
// ---------------------------------------------------------------------------
static constexpr int SMEMY = 4096 * 4 + 80;

__global__ __launch_bounds__(256) void ln_y_kernel(
    const float* __restrict__ feat, const float* __restrict__ gamma,
    const float* __restrict__ beta, float* __restrict__ out)
{
    extern __shared__ float sm[];
    float* s_x = sm;
    float* s_red = sm + 4096;

    const int b = blockIdx.x, tid = threadIdx.x;
    const int wid = tid >> 5, lane = tid & 31;
    const float4* x4 = (const float4*)(feat + (size_t)b * Mc);

    {   // zero this batch's out row (head REDG-accumulates into it)
        float4* o4 = (float4*)(out + (size_t)b * 4096);
        #pragma unroll
        for (int j = 0; j < 4; j++)
            o4[tid + j * 256] = make_float4(0.f, 0.f, 0.f, 0.f);
    }

    float sum = 0.f, sq = 0.f;
    for (int i = tid; i < 1024; i += 256) {
        float4 v = x4[i];
        *(float4*)&s_x[i * 4] = v;
        sum += v.x + v.y + v.z + v.w;
        sq  += v.x*v.x + v.y*v.y + v.z*v.z + v.w*v.w;
    }
    #pragma unroll
    for (int o = 16; o; o >>= 1) {
        sum += __shfl_xor_sync(~0u, sum, o);
        sq  += __shfl_xor_sync(~0u, sq,  o);
    }
    if (lane == 0) { s_red[wid] = sum; s_red[wid + 8] = sq; }
    __syncthreads();
    if (tid == 0) {
        float S = 0.f, Q = 0.f;
        #pragma unroll
        for (int i = 0; i < 8; i++) { S += s_red[i]; Q += s_red[i + 8]; }
        float mu = S * (1.f / Mc);
        s_red[16] = mu;
        s_red[17] = rsqrtf(Q * (1.f / Mc) - mu * mu + 1e-5f);
    }
    __syncthreads();
    const float mu = s_red[16], rstd = s_red[17];
    float4* y4 = (float4*)(g_y + (size_t)b * Mc);
    const float4* g4 = (const float4*)gamma;
    const float4* b4 = (const float4*)beta;
    for (int i = tid; i < 1024; i += 256) {
        float4 v = *(float4*)&s_x[i * 4];
        float4 g = g4[i], bb = b4[i], y;
        y.x = tf32r((v.x - mu) * rstd * g.x + bb.x);
        y.y = tf32r((v.y - mu) * rstd * g.y + bb.y);
        y.z = tf32r((v.z - mu) * rstd * g.z + bb.z);
        y.w = tf32r((v.w - mu) * rstd * g.w + bb.w);
        y4[i] = y;
    }
}

// ---------------------------------------------------------------------------
// Kernel 1: per-(b,h) head (R9 memory map) with warp-specialized A/B phases.
// Warps 0-3: {y,wq,wk} staging -> q GEMM -> q store + key GEMM.
// Warps 4-7: {feat} staging -> gather kf -> conv.
// smem (floats):
//   @0     kf[64][68] — gathered feats; S overlay (P3+); hout overlay (P6)
//   @4352  feat[4096] — raw feats; vT overlay in phase B
//   @8704  y[64][68]  — dies after q GEMM; then keyT@8704 + q@11008;
//                        after P3: wfc[64][68]@8704
//   @13312 wk[32][68]
//   @15488 wq[32][68]
//   @17664 wv[16]
// total 17680 floats = 70.7 KB -> 3 CTA/SM.
// ---------------------------------------------------------------------------
static constexpr int SMEM2 = 17680 * 4;

__global__ __launch_bounds__(256) void head_mma(
    const float* __restrict__ feat, const int* __restrict__ sidx,
    const float* __restrict__ Wk, const float* __restrict__ Wv1,
    const float* __restrict__ Wv2, const float* __restrict__ Wq,
    const float* __restrict__ Wfc,
    float* __restrict__ out, float* __restrict__ attn_out)
{
    extern __shared__ float sm[];
    float* s_kf   = sm;            // [64][68]
    float* s_S    = sm;            // overlay
    float* s_vT   = sm + 4352;     // [p][n] pitch 68
    float* s_feat = sm + 4352;
    float* s_y    = sm + 8704;     // dies after q GEMM
    float* s_keyT = sm + 8704;     // [n][d] pitch 36
    float* s_q    = sm + 11008;    // [q][d] pitch 36
    float* s_wfc  = sm + 8704;     // [o][p] pitch 68 (after P3)
    float* s_wk   = sm + 13312;    // [d][k] pitch 68
    float* s_wq   = sm + 15488;    // [e][k] pitch 68 (raw)
    float* s_wv   = sm + 17664;    // wv1[12], wv2[4]

    const int h = blockIdx.x, b = blockIdx.y, tid = threadIdx.x;
    const int wid = tid >> 5, lane = tid & 31;
    const int lr = lane >> 2, lc = lane & 3;
    const int* idx = sidx + (size_t)h * Mc;
    const uint32_t sbase = smem_u32(sm);

    float qacc[4][4] = {};

    // ======================= PHASE A (warp-specialized) =======================
    if (wid < 4) {
        const int t4 = tid;                      // 0..127
        // ---- stage y (1024 cp16), wq (512), wk (512) — one group ----
        const float* yg = g_y + (size_t)b * Mc;
        #pragma unroll
        for (int j = 0; j < 8; j++) {
            int i = t4 + j * 128;                // 0..1023
            int n = i >> 4, k4 = i & 15;
            cp16(sbase + (uint32_t)(8704 + n * 68 + k4 * 4) * 4, yg + i * 4);
        }
        #pragma unroll
        for (int j = 0; j < 4; j++) {
            int i = t4 + j * 128;                // 0..511
            int e = i >> 4, k4 = i & 15;
            cp16(sbase + (uint32_t)(15488 + e * 68 + k4 * 4) * 4,
                 Wq + (size_t)(h * 32 + e) * 64 + k4 * 4);
        }
        #pragma unroll
        for (int j = 0; j < 4; j++) {
            int i = t4 + j * 128;                // 0..511
            int d = i >> 4, k4 = i & 15;
            cp16(sbase + (uint32_t)(13312 + d * 68 + k4 * 4) * 4,
                 Wk + (size_t)(h * 32 + d) * 64 + k4 * 4);
        }
        CP_COMMIT();
        CP_WAIT(0);
        BAR_SYNC(1, 128);

        // ---- q GEMM (4 warps): rows qm=wid*16, d-tiles t*8, t<4 ----
        const int qm = wid * 16;
        #pragma unroll
        for (int k8 = 0; k8 < 8; k8++) {
            const int k0 = k8 * 8;
            uint32_t a[4];
            a[0] = __float_as_uint(s_y[(qm + lr)     * 68 + k0 + lc]);
            a[1] = __float_as_uint(s_y[(qm + lr + 8) * 68 + k0 + lc]);
            a[2] = __float_as_uint(s_y[(qm + lr)     * 68 + k0 + lc + 4]);
            a[3] = __float_as_uint(s_y[(qm + lr + 8) * 68 + k0 + lc + 4]);
            #pragma unroll
            for (int t = 0; t < 4; t++) {
                uint32_t bfr[2];
                bfr[0] = __float_as_uint(tf32r(s_wq[(t * 8 + lr) * 68 + k0 + lc]));
                bfr[1] = __float_as_uint(tf32r(s_wq[(t * 8 + lr) * 68 + k0 + lc + 4]));
                mma16n8k8(qacc[t], a, bfr);
            }
        }
    } else {
        const int t4 = tid - 128;                // 0..127
        // ---- stage feat (1024 cp16) — one group ----
        const float* xg = feat + (size_t)b * Mc;
        #pragma unroll
        for (int j = 0; j < 8; j++) {
            int i = t4 + j * 128;
            cp16(sbase + (uint32_t)(4352 + i * 4) * 4, xg + i * 4);
        }
        CP_COMMIT();
        // wv (plain stores; consumed after full __syncthreads below)
        if (t4 < 12) s_wv[t4] = Wv1[h * 12 + t4];
        if (t4 >= 32 && t4 < 36) s_wv[12 + t4 - 32] = Wv2[h * 4 + t4 - 32];
        CP_WAIT(0);
        BAR_SYNC(2, 128);

        // ---- gather kf from smem feat; zero conv pad ----
        const int4* idx4 = (const int4*)idx;
        #pragma unroll
        for (int j = 0; j < 8; j++) {
            int i = t4 + j * 128;                // 0..1023
            int4 v = idx4[i];
            int n = i >> 4, k = (i & 15) * 4;
            float4 g = make_float4(s_feat[v.x], s_feat[v.y], s_feat[v.z], s_feat[v.w]);
            *(float4*)&s_kf[n * 68 + k] = g;
        }
        s_kf[(t4 >> 1) * 68 + 64 + (t4 & 1)] = 0.f;
    }
    __syncthreads();   // kf, y, wk, wv all visible CTA-wide

    // ======================= PHASE B (warp-specialized) =======================
    if (wid < 4) {
        // ---- q frag store (x 1/64), 4 d-tiles ----
        const int qm = wid * 16;
        #pragma unroll
        for (int t = 0; t < 4; t++) {
            const int d = t * 8 + lc * 2;
            s_q[(qm + lr) * 36 + d]         = tf32r(qacc[t][0] * 0.015625f);
            s_q[(qm + lr) * 36 + d + 1]     = tf32r(qacc[t][1] * 0.015625f);
            s_q[(qm + lr + 8) * 36 + d]     = tf32r(qacc[t][2] * 0.015625f);
            s_q[(qm + lr + 8) * 36 + d + 1] = tf32r(qacc[t][3] * 0.015625f);
        }
        // ---- key GEMM (4 warps): d tile m0=(wid&1)*16; n tiles nb+t*16 ----
        const int m0 = (wid & 1) * 16;
        const int nb = (wid >> 1) * 8;
        float acc[4][4] = {};
        #pragma unroll
        for (int k8 = 0; k8 < 8; k8++) {
            const int k0 = k8 * 8;
            uint32_t a[4];
            a[0] = __float_as_uint(tf32r(s_wk[(m0 + lr)     * 68 + k0 + lc]));
            a[1] = __float_as_uint(tf32r(s_wk[(m0 + lr + 8) * 68 + k0 + lc]));
            a[2] = __float_as_uint(tf32r(s_wk[(m0 + lr)     * 68 + k0 + lc + 4]));
            a[3] = __float_as_uint(tf32r(s_wk[(m0 + lr + 8) * 68 + k0 + lc + 4]));
            #pragma unroll
            for (int t = 0; t < 4; t++) {
                const int nn = nb + t * 16;
                uint32_t bfr[2];
                bfr[0] = __float_as_uint(tf32r(s_kf[(nn + lr) * 68 + k0 + lc]));
                bfr[1] = __float_as_uint(tf32r(s_kf[(nn + lr) * 68 + k0 + lc + 4]));
                mma16n8k8(acc[t], a, bfr);
            }
        }
        #pragma unroll
        for (int t = 0; t < 4; t++) {
            const int n = nb + t * 16 + lc * 2, d = m0 + lr;
            s_keyT[n * 36 + d]           = tf32r(acc[t][0]);
            s_keyT[(n + 1) * 36 + d]     = tf32r(acc[t][1]);
            s_keyT[n * 36 + d + 8]       = tf32r(acc[t][2]);
            s_keyT[(n + 1) * 36 + d + 8] = tf32r(acc[t][3]);
        }
    } else {
        // ---- conv (4 warps, 128 threads): n = t4>>1, p0 = (t4&1)*32 ----
        const int t4 = tid - 128;
        const int n = t4 >> 1, p0 = (t4 & 1) * 32;
        const float* kr = s_kf + n * 68;
        float w0[4], w1[4], w2[4], w3[4];
        #pragma unroll
        for (int d = 0; d < 4; d++) {
            w0[d] = s_wv[d * 3]; w1[d] = s_wv[d * 3 + 1];
            w2[d] = s_wv[d * 3 + 2]; w3[d] = s_wv[12 + d];
        }
        float x0 = kr[p0], x1 = kr[p0 + 1];
        #pragma unroll
        for (int i = 0; i < 32; i++) {
            float x2 = kr[p0 + i + 2];
            float acc = x0;
            #pragma unroll
            for (int d = 0; d < 4; d++)
                acc += fmaxf(x0 * w0[d] + x1 * w1[d] + x2 * w2[d], 0.f) * w3[d];
            s_vT[(p0 + i) * 68 + n] = tf32r(acc);
            x0 = x1; x1 = x2;
        }
    }
    __syncthreads();

    const int m0 = (wid >> 1) * 16;       // q tile
    const int nb4 = (wid & 1) * 4;        // 4 n-tiles

    // ---- P3: S[q][n] = sum_d q[q][d] * keyT[n][d] -> S overlay (kf dead) ----
    {
        float acc[4][4] = {};
        #pragma unroll
        for (int k8 = 0; k8 < 4; k8++) {
            const int k0 = k8 * 8;
            uint32_t a[4];
            a[0] = __float_as_uint(s_q[(m0 + lr)     * 36 + k0 + lc]);
            a[1] = __float_as_uint(s_q[(m0 + lr + 8) * 36 + k0 + lc]);
            a[2] = __float_as_uint(s_q[(m0 + lr)     * 36 + k0 + lc + 4]);
            a[3] = __float_as_uint(s_q[(m0 + lr + 8) * 36 + k0 + lc + 4]);
            #pragma unroll
            for (int j = 0; j < 4; j++) {
                const int nn = (nb4 + j) * 8;
                uint32_t bfr[2];
                bfr[0] = __float_as_uint(s_keyT[(nn + lr) * 36 + k0 + lc]);
                bfr[1] = __float_as_uint(s_keyT[(nn + lr) * 36 + k0 + lc + 4]);
                mma16n8k8(acc[j], a, bfr);
            }
        }
        #pragma unroll
        for (int j = 0; j < 4; j++) {
            const int col = (nb4 + j) * 8 + lc * 2;
            *(float2*)&s_S[(m0 + lr)     * 68 + col] = make_float2(acc[j][0], acc[j][1]);
            *(float2*)&s_S[(m0 + lr + 8) * 68 + col] = make_float2(acc[j][2], acc[j][3]);
        }
    }
    __syncthreads();   // keyT/q dead

    // ---- stage Wfc slice into dead keyT/q region (overlaps softmax) ----
    {
        #pragma unroll
        for (int j = 0; j < 4; j++) {
            int i = tid + j * 256;               // 0..1023
            int o = i >> 4, p4 = i & 15;
            cp16(sbase + (uint32_t)(8704 + o * 68 + p4 * 4) * 4,
                 Wfc + (size_t)o * 512 + h * 64 + p4 * 4);
        }
        CP_COMMIT();
    }

    // ---- P4: softmax rows of S; global attn fp32, smem tf32 ----
    {
        const int r = tid >> 2, s3 = tid & 3;
        float* row = s_S + r * 68 + s3 * 16;
        float4 v0 = *(float4*)&row[0], v1 = *(float4*)&row[4];
        float4 v2 = *(float4*)&row[8], v3 = *(float4*)&row[12];
        float mx = fmaxf(fmaxf(fmaxf(v0.x, v0.y), fmaxf(v0.z, v0.w)),
                         fmaxf(fmaxf(v1.x, v1.y), fmaxf(v1.z, v1.w)));
        mx = fmaxf(mx, fmaxf(fmaxf(fmaxf(v2.x, v2.y), fmaxf(v2.z, v2.w)),
                             fmaxf(fmaxf(v3.x, v3.y), fmaxf(v3.z, v3.w))));
        mx = fmaxf(mx, __shfl_xor_sync(~0u, mx, 1));
        mx = fmaxf(mx, __shfl_xor_sync(~0u, mx, 2));
        float e[16];
        e[0]=__expf(v0.x-mx); e[1]=__expf(v0.y-mx); e[2]=__expf(v0.z-mx); e[3]=__expf(v0.w-mx);
        e[4]=__expf(v1.x-mx); e[5]=__expf(v1.y-mx); e[6]=__expf(v1.z-mx); e[7]=__expf(v1.w-mx);
        e[8]=__expf(v2.x-mx); e[9]=__expf(v2.y-mx); e[10]=__expf(v2.z-mx); e[11]=__expf(v2.w-mx);
        e[12]=__expf(v3.x-mx); e[13]=__expf(v3.y-mx); e[14]=__expf(v3.z-mx); e[15]=__expf(v3.w-mx);
        float ssum = 0.f;
        #pragma unroll
        for (int i = 0; i < 16; i++) ssum += e[i];
        ssum += __shfl_xor_sync(~0u, ssum, 1);
        ssum += __shfl_xor_sync(~0u, ssum, 2);
        const float inv = 1.f / ssum;
        float* gattn = attn_out + (((size_t)(b * Hc + h) * Nc + r) * Nc) + s3 * 16;
        #pragma unroll
        for (int u = 0; u < 4; u++) {
            float p0 = e[4*u] * inv, p1 = e[4*u+1] * inv,
                  p2 = e[4*u+2] * inv, p3 = e[4*u+3] * inv;
            *(float4*)&gattn[4 * u] = make_float4(p0, p1, p2, p3);
            *(float4*)&row[4 * u]   = make_float4(tf32r(p0), tf32r(p1), tf32r(p2), tf32r(p3));
        }
    }
    __syncthreads();

    // ---- P5: hout[q][p] = sum_n attn[q][n] * vT[p][n] (registers) ----
    float hacc[4][4] = {};
    {
        #pragma unroll
        for (int k8 = 0; k8 < 8; k8++) {
            const int k0 = k8 * 8;
            uint32_t a[4];
            a[0] = __float_as_uint(s_S[(m0 + lr)     * 68 + k0 + lc]);
            a[1] = __float_as_uint(s_S[(m0 + lr + 8) * 68 + k0 + lc]);
            a[2] = __float_as_uint(s_S[(m0 + lr)     * 68 + k0 + lc + 4]);
            a[3] = __float_as_uint(s_S[(m0 + lr + 8) * 68 + k0 + lc + 4]);
            #pragma unroll
            for (int j = 0; j < 4; j++) {
                const int pp = (nb4 + j) * 8;
                uint32_t bfr[2];
                bfr[0] = __float_as_uint(s_vT[(pp + lr) * 68 + k0 + lc]);
                bfr[1] = __float_as_uint(s_vT[(pp + lr) * 68 + k0 + lc + 4]);
                mma16n8k8(hacc[j], a, bfr);
            }
        }
    }
    CP_WAIT(0);        // wfc landed
    __syncthreads();   // all P5 reads of S done -> hout overlay safe

    // ---- store hout (tf32) into S region ----
    {
        #pragma unroll
        for (int j = 0; j < 4; j++) {
            const int p = (nb4 + j) * 8 + lc * 2;
            *(float2*)&s_S[(m0 + lr) * 68 + p] =
                make_float2(tf32r(hacc[j][0]), tf32r(hacc[j][1]));
            *(float2*)&s_S[(m0 + lr + 8) * 68 + p] =
                make_float2(tf32r(hacc[j][2]), tf32r(hacc[j][3]));
        }
    }
    __syncthreads();

    // ---- P6: FC partial  po[n][o] = sum_p hout[n][p] * wfc[o][p]; REDG ----
    {
        const int fm = (wid >> 1) * 16;      // n rows
        const int fo = (wid & 1) * 32;       // o cols (4 n8-tiles)
        float acc[4][4] = {};
        #pragma unroll
        for (int k8 = 0; k8 < 8; k8++) {
            const int k0 = k8 * 8;
            uint32_t a[4];
            a[0] = __float_as_uint(s_S[(fm + lr)     * 68 + k0 + lc]);
            a[1] = __float_as_uint(s_S[(fm + lr + 8) * 68 + k0 + lc]);
            a[2] = __float_as_uint(s_S[(fm + lr)     * 68 + k0 + lc + 4]);
            a[3] = __float_as_uint(s_S[(fm + lr + 8) * 68 + k0 + lc + 4]);
            #pragma unroll
            for (int t = 0; t < 4; t++) {
                uint32_t bfr[2];
                bfr[0] = __float_as_uint(tf32r(s_wfc[(fo + t * 8 + lr) * 68 + k0 + lc]));
                bfr[1] = __float_as_uint(tf32r(s_wfc[(fo + t * 8 + lr) * 68 + k0 + lc + 4]));
                mma16n8k8(acc[t], a, bfr);
            }
        }
        float* ob = out + (size_t)b * 4096;
        #pragma unroll
        for (int t = 0; t < 4; t++) {
            const int o = fo + t * 8 + lc * 2;
            redg_add(ob + (fm + lr) * 64 + o,     acc[t][0]);
            redg_add(ob + (fm + lr) * 64 + o + 1, acc[t][1]);
            redg_add(ob + (fm + lr + 8) * 64 + o,     acc[t][2]);
            redg_add(ob + (fm + lr + 8) * 64 + o + 1, acc[t][3]);
        }
    }
}

// ---------------------------------------------------------------------------
extern "C" void kernel_launch(void* const* d_in, const int* in_sizes, int n_in,
                              void* d_out, int out_size) {
    const float* feat  = (const float*)d_in[0];
    const int*   sidx  = (const int*)  d_in[1];
    const float* gamma = (const float*)d_in[2];
    const float* beta  = (const float*)d_in[3];
    const float* Wq    = (const float*)d_in[4];
    const float* Wk    = (const float*)d_in[5];
    const float* Wv1   = (const float*)d_in[6];
    const float* Wv2   = (const float*)d_in[7];
    const float* Wfc   = (const float*)d_in[8];

    float* out  = (float*)d_out;
    float* attn = out + (size_t)Bc * Nc * 64;

    cudaFuncSetAttribute(ln_y_kernel, cudaFuncAttributeMaxDynamicSharedMemorySize, SMEMY);
    cudaFuncSetAttribute(head_mma,    cudaFuncAttributeMaxDynamicSharedMemorySize, SMEM2);

    ln_y_kernel<<<Bc, 256, SMEMY>>>(feat, gamma, beta, out);
    head_mma<<<dim3(Hc, Bc), 256, SMEM2>>>(feat, sidx, Wk, Wv1, Wv2, Wq, Wfc, out, attn);
}

// round 13
// speedup vs baseline: 1.6620x; 1.0005x over previous
#include <cuda_runtime.h>
#include <math.h>
#include <stdint.h>

#define Bc 512
#define Mc 4096
#define Nc 64
#define Hc 8

// Scratch (device globals, allocation-free rule)
__device__ float g_y[(size_t)Bc * Mc];       // 8 MB, LN'd features (tf32, affine)
__device__ float g_wqB[Hc * 8 * 4 * 64];     // q-GEMM B frags  [h][k8][t4][lane*2]
__device__ float g_wkA[Hc * 8 * 2 * 128];    // key-GEMM A frags [h][k8][mt2][lane*4]
__device__ float g_wfcB[Hc * 8 * 8 * 64];    // FC B frags      [h][k8][ot8][lane*2]

__device__ __forceinline__ float tf32r(float x) {
    float r; asm("cvt.rna.tf32.f32 %0, %1;" : "=f"(r) : "f"(x)); return r;
}
__device__ __forceinline__ void mma16n8k8(float* c, const uint32_t* a, const uint32_t* b) {
    asm volatile(
        "mma.sync.aligned.m16n8k8.row.col.f32.tf32.tf32.f32 "
        "{%0,%1,%2,%3}, {%4,%5,%6,%7}, {%8,%9}, {%0,%1,%2,%3};"
        : "+f"(c[0]), "+f"(c[1]), "+f"(c[2]), "+f"(c[3])
        : "r"(a[0]), "r"(a[1]), "r"(a[2]), "r"(a[3]), "r"(b[0]), "r"(b[1]));
}
__device__ __forceinline__ uint32_t smem_u32(const void* p) {
    uint32_t a;
    asm("{ .reg .u64 t; cvta.to.shared.u64 t, %1; cvt.u32.u64 %0, t; }" : "=r"(a) : "l"(p));
    return a;
}
__device__ __forceinline__ void cp16(uint32_t s, const void* g) {
    asm volatile("cp.async.cg.shared.global [%0], [%1], 16;" :: "r"(s), "l"(g));
}
__device__ __forceinline__ void redg_add(float* g, float v) {
    asm volatile("red.global.add.f32 [%0], %1;" :: "l"(g), "f"(v) : "memory");
}
#define CP_COMMIT()  asm volatile("cp.async.commit_group;" ::: "memory")
#define CP_WAIT(n)   asm volatile("cp.async.wait_group %0;" :: "n"(n) : "memory")
#define BAR_SYNC(id, cnt) asm volatile("bar.sync %0, %1;" :: "r"(id), "r"(cnt) : "memory")

// ---------------------------------------------------------------------------
// Kernel P: pack weights into fragment-order global arrays (tf32-rounded).
// grid = Hc, 256 threads.
// ---------------------------------------------------------------------------
__global__ __launch_bounds__(256) void pack_w(
    const float* __restrict__ Wq, const float* __restrict__ Wk,
    const float* __restrict__ Wfc)
{
    const int h = blockIdx.x, tid = threadIdx.x;
    // g_wqB: [k8][t<4][lane]{2} : Wq[(h*32 + t*8+lr)][k8*8+lc(+4)]
    for (int i = tid; i < 1024; i += 256) {
        int k8 = i >> 7, t = (i >> 5) & 3, lane = i & 31;
        int lr = lane >> 2, lc = lane & 3;
        const float* src = Wq + (size_t)(h * 32 + t * 8 + lr) * 64 + k8 * 8 + lc;
        float2 v = make_float2(tf32r(src[0]), tf32r(src[4]));
        *(float2*)&g_wqB[(size_t)h * 2048 + i * 2] = v;
    }
    // g_wkA: [k8][mt<2][lane]{4} : a0,a1,a2,a3
    for (int i = tid; i < 512; i += 256) {
        int k8 = i >> 6, mt = (i >> 5) & 1, lane = i & 31;
        int lr = lane >> 2, lc = lane & 3;
        const float* src = Wk + (size_t)h * 2048 + (mt * 16 + lr) * 64 + k8 * 8 + lc;
        float4 v = make_float4(tf32r(src[0]), tf32r(src[8 * 64]),
                               tf32r(src[4]), tf32r(src[8 * 64 + 4]));
        *(float4*)&g_wkA[(size_t)h * 2048 + i * 4] = v;
    }
    // g_wfcB: [k8][ot<8][lane]{2} : Wfc[(ot*8+lr)][h*64 + k8*8+lc(+4)]
    for (int i = tid; i < 2048; i += 256) {
        int k8 = i >> 8, ot = (i >> 5) & 7, lane = i & 31;
        int lr = lane >> 2, lc = lane & 3;
        const float* src = Wfc + (size_t)(ot * 8 + lr) * 512 + h * 64 + k8 * 8 + lc;
        float2 v = make_float2(tf32r(src[0]), tf32r(src[4]));
        *(float2*)&g_wfcB[(size_t)h * 4096 + i * 2] = v;
    }
}

// ---------------------------------------------------------------------------
// Kernel 0: LayerNorm -> g_y (tf32, affine) AND zero out[b] row. grid=B.
// ---------------------------------------------------------------------------
static constexpr int SMEMY = 4096 * 4 + 80;

__global__ __launch_bounds__(256) void ln_y_kernel(
    const float* __restrict__ feat, const float* __restrict__ gamma,
    const float* __restrict__ beta, float* __restrict__ out)
{
    extern __shared__ float sm[];
    float* s_x = sm;
    float* s_red = sm + 4096;

    const int b = blockIdx.x, tid = threadIdx.x;
    const int wid = tid >> 5, lane = tid & 31;
    const float4* x4 = (const float4*)(feat + (size_t)b * Mc);

    {
        float4* o4 = (float4*)(out + (size_t)b * 4096);
        #pragma unroll
        for (int j = 0; j < 4; j++)
            o4[tid + j * 256] = make_float4(0.f, 0.f, 0.f, 0.f);
    }

    float sum = 0.f, sq = 0.f;
    for (int i = tid; i < 1024; i += 256) {
        float4 v = x4[i];
        *(float4*)&s_x[i * 4] = v;
        sum += v.x + v.y + v.z + v.w;
        sq  += v.x*v.x + v.y*v.y + v.z*v.z + v.w*v.w;
    }
    #pragma unroll
    for (int o = 16; o; o >>= 1) {
        sum += __shfl_xor_sync(~0u, sum, o);
        sq  += __shfl_xor_sync(~0u, sq,  o);
    }
    if (lane == 0) { s_red[wid] = sum; s_red[wid + 8] = sq; }
    __syncthreads();
    if (tid == 0) {
        float S = 0.f, Q = 0.f;
        #pragma unroll
        for (int i = 0; i < 8; i++) { S += s_red[i]; Q += s_red[i + 8]; }
        float mu = S * (1.f / Mc);
        s_red[16] = mu;
        s_red[17] = rsqrtf(Q * (1.f / Mc) - mu * mu + 1e-5f);
    }
    __syncthreads();
    const float mu = s_red[16], rstd = s_red[17];
    float4* y4 = (float4*)(g_y + (size_t)b * Mc);
    const float4* g4 = (const float4*)gamma;
    const float4* b4 = (const float4*)beta;
    for (int i = tid; i < 1024; i += 256) {
        float4 v = *(float4*)&s_x[i * 4];
        float4 g = g4[i], bb = b4[i], y;
        y.x = tf32r((v.x - mu) * rstd * g.x + bb.x);
        y.y = tf32r((v.y - mu) * rstd * g.y + bb.y);
        y.z = tf32r((v.z - mu) * rstd * g.z + bb.z);
        y.w = tf32r((v.w - mu) * rstd * g.w + bb.w);
        y4[i] = y;
    }
}

// ---------------------------------------------------------------------------
// Kernel 1: per-(b,h) head; weights via packed coalesced global frags (L1).
// Warp-specialized A/B phases (R12). smem:
//   @0     kf[64][68]  — gathered feats; S overlay; hout overlay
//   @4352  feat[4096]  — raw feats; vT overlay in phase B
//   @8704  y[64][68]   — dies after q GEMM; then keyT[64][36]@8704 + q@11008
//   @13312 wv[16]
// total 13328 floats = 53.3 KB -> 4 CTA/SM.
// ---------------------------------------------------------------------------
static constexpr int SMEM2 = 13328 * 4;

__global__ __launch_bounds__(256, 4) void head_mma(
    const float* __restrict__ feat, const int* __restrict__ sidx,
    const float* __restrict__ Wv1, const float* __restrict__ Wv2,
    float* __restrict__ out, float* __restrict__ attn_out)
{
    extern __shared__ float sm[];
    float* s_kf   = sm;            // [64][68]
    float* s_S    = sm;            // overlay
    float* s_vT   = sm + 4352;     // [p][n] pitch 68
    float* s_feat = sm + 4352;
    float* s_y    = sm + 8704;     // dies after q GEMM
    float* s_keyT = sm + 8704;     // [n][d] pitch 36
    float* s_q    = sm + 11008;    // [q][d] pitch 36
    float* s_wv   = sm + 13312;    // wv1[12], wv2[4]

    const int b = blockIdx.x, h = blockIdx.y, tid = threadIdx.x;
    const int wid = tid >> 5, lane = tid & 31;
    const int lr = lane >> 2, lc = lane & 3;
    const int* idx = sidx + (size_t)h * Mc;
    const uint32_t sbase = smem_u32(sm);

    float qacc[4][4] = {};

    // ======================= PHASE A (warp-specialized) =======================
    if (wid < 4) {
        const int t4 = tid;                      // 0..127
        const float* yg = g_y + (size_t)b * Mc;
        #pragma unroll
        for (int j = 0; j < 8; j++) {
            int i = t4 + j * 128;                // 0..1023
            int n = i >> 4, k4 = i & 15;
            cp16(sbase + (uint32_t)(8704 + n * 68 + k4 * 4) * 4, yg + i * 4);
        }
        CP_COMMIT();
        CP_WAIT(0);
        BAR_SYNC(1, 128);

        // ---- q GEMM: rows qm=wid*16; b-frags from g_wqB (coalesced LDG.64) ----
        const int qm = wid * 16;
        const float* wq = g_wqB + (size_t)h * 2048;
        #pragma unroll
        for (int k8 = 0; k8 < 8; k8++) {
            const int k0 = k8 * 8;
            uint32_t a[4];
            a[0] = __float_as_uint(s_y[(qm + lr)     * 68 + k0 + lc]);
            a[1] = __float_as_uint(s_y[(qm + lr + 8) * 68 + k0 + lc]);
            a[2] = __float_as_uint(s_y[(qm + lr)     * 68 + k0 + lc + 4]);
            a[3] = __float_as_uint(s_y[(qm + lr + 8) * 68 + k0 + lc + 4]);
            #pragma unroll
            for (int t = 0; t < 4; t++) {
                float2 w = *(const float2*)&wq[(k8 * 4 + t) * 64 + lane * 2];
                uint32_t bfr[2] = { __float_as_uint(w.x), __float_as_uint(w.y) };
                mma16n8k8(qacc[t], a, bfr);
            }
        }
    } else {
        const int t4 = tid - 128;                // 0..127
        const float* xg = feat + (size_t)b * Mc;
        #pragma unroll
        for (int j = 0; j < 8; j++) {
            int i = t4 + j * 128;
            cp16(sbase + (uint32_t)(4352 + i * 4) * 4, xg + i * 4);
        }
        CP_COMMIT();
        if (t4 < 12) s_wv[t4] = Wv1[h * 12 + t4];
        if (t4 >= 32 && t4 < 36) s_wv[12 + t4 - 32] = Wv2[h * 4 + t4 - 32];
        CP_WAIT(0);
        BAR_SYNC(2, 128);

        // ---- gather kf from smem feat; zero conv pad ----
        const int4* idx4 = (const int4*)idx;
        #pragma unroll
        for (int j = 0; j < 8; j++) {
            int i = t4 + j * 128;                // 0..1023
            int4 v = idx4[i];
            int n = i >> 4, k = (i & 15) * 4;
            float4 g = make_float4(s_feat[v.x], s_feat[v.y], s_feat[v.z], s_feat[v.w]);
            *(float4*)&s_kf[n * 68 + k] = g;
        }
        s_kf[(t4 >> 1) * 68 + 64 + (t4 & 1)] = 0.f;
    }
    __syncthreads();   // kf, y, wv visible CTA-wide

    // ======================= PHASE B (warp-specialized) =======================
    if (wid < 4) {
        // ---- q frag store (x 1/64) ----
        const int qm = wid * 16;
        #pragma unroll
        for (int t = 0; t < 4; t++) {
            const int d = t * 8 + lc * 2;
            s_q[(qm + lr) * 36 + d]         = tf32r(qacc[t][0] * 0.015625f);
            s_q[(qm + lr) * 36 + d + 1]     = tf32r(qacc[t][1] * 0.015625f);
            s_q[(qm + lr + 8) * 36 + d]     = tf32r(qacc[t][2] * 0.015625f);
            s_q[(qm + lr + 8) * 36 + d + 1] = tf32r(qacc[t][3] * 0.015625f);
        }
        // ---- key GEMM: a-frags from g_wkA (coalesced LDG.128) ----
        const int mt = wid & 1;
        const int m0 = mt * 16;
        const int nb = (wid >> 1) * 8;
        const float* wk = g_wkA + (size_t)h * 2048;
        float acc[4][4] = {};
        #pragma unroll
        for (int k8 = 0; k8 < 8; k8++) {
            const int k0 = k8 * 8;
            float4 w = *(const float4*)&wk[(k8 * 2 + mt) * 128 + lane * 4];
            uint32_t a[4] = { __float_as_uint(w.x), __float_as_uint(w.y),
                              __float_as_uint(w.z), __float_as_uint(w.w) };
            #pragma unroll
            for (int t = 0; t < 4; t++) {
                const int nn = nb + t * 16;
                uint32_t bfr[2];
                bfr[0] = __float_as_uint(tf32r(s_kf[(nn + lr) * 68 + k0 + lc]));
                bfr[1] = __float_as_uint(tf32r(s_kf[(nn + lr) * 68 + k0 + lc + 4]));
                mma16n8k8(acc[t], a, bfr);
            }
        }
        #pragma unroll
        for (int t = 0; t < 4; t++) {
            const int n = nb + t * 16 + lc * 2, d = m0 + lr;
            s_keyT[n * 36 + d]           = tf32r(acc[t][0]);
            s_keyT[(n + 1) * 36 + d]     = tf32r(acc[t][1]);
            s_keyT[n * 36 + d + 8]       = tf32r(acc[t][2]);
            s_keyT[(n + 1) * 36 + d + 8] = tf32r(acc[t][3]);
        }
    } else {
        // ---- conv (128 threads): n = t4>>1, p0 = (t4&1)*32 ----
        const int t4 = tid - 128;
        const int n = t4 >> 1, p0 = (t4 & 1) * 32;
        const float* kr = s_kf + n * 68;
        float w0[4], w1[4], w2[4], w3[4];
        #pragma unroll
        for (int d = 0; d < 4; d++) {
            w0[d] = s_wv[d * 3]; w1[d] = s_wv[d * 3 + 1];
            w2[d] = s_wv[d * 3 + 2]; w3[d] = s_wv[12 + d];
        }
        float x0 = kr[p0], x1 = kr[p0 + 1];
        #pragma unroll
        for (int i = 0; i < 32; i++) {
            float x2 = kr[p0 + i + 2];
            float acc = x0;
            #pragma unroll
            for (int d = 0; d < 4; d++)
                acc += fmaxf(x0 * w0[d] + x1 * w1[d] + x2 * w2[d], 0.f) * w3[d];
            s_vT[(p0 + i) * 68 + n] = tf32r(acc);
            x0 = x1; x1 = x2;
        }
    }
    __syncthreads();

    const int m0 = (wid >> 1) * 16;       // q tile
    const int nb4 = (wid & 1) * 4;        // 4 n-tiles

    // ---- P3: S[q][n] = sum_d q[q][d] * keyT[n][d] -> S overlay (kf dead) ----
    {
        float acc[4][4] = {};
        #pragma unroll
        for (int k8 = 0; k8 < 4; k8++) {
            const int k0 = k8 * 8;
            uint32_t a[4];
            a[0] = __float_as_uint(s_q[(m0 + lr)     * 36 + k0 + lc]);
            a[1] = __float_as_uint(s_q[(m0 + lr + 8) * 36 + k0 + lc]);
            a[2] = __float_as_uint(s_q[(m0 + lr)     * 36 + k0 + lc + 4]);
            a[3] = __float_as_uint(s_q[(m0 + lr + 8) * 36 + k0 + lc + 4]);
            #pragma unroll
            for (int j = 0; j < 4; j++) {
                const int nn = (nb4 + j) * 8;
                uint32_t bfr[2];
                bfr[0] = __float_as_uint(s_keyT[(nn + lr) * 36 + k0 + lc]);
                bfr[1] = __float_as_uint(s_keyT[(nn + lr) * 36 + k0 + lc + 4]);
                mma16n8k8(acc[j], a, bfr);
            }
        }
        #pragma unroll
        for (int j = 0; j < 4; j++) {
            const int col = (nb4 + j) * 8 + lc * 2;
            *(float2*)&s_S[(m0 + lr)     * 68 + col] = make_float2(acc[j][0], acc[j][1]);
            *(float2*)&s_S[(m0 + lr + 8) * 68 + col] = make_float2(acc[j][2], acc[j][3]);
        }
    }
    __syncthreads();

    // ---- P4: softmax rows of S; global attn fp32, smem tf32 ----
    {
        const int r = tid >> 2, s3 = tid & 3;
        float* row = s_S + r * 68 + s3 * 16;
        float4 v0 = *(float4*)&row[0], v1 = *(float4*)&row[4];
        float4 v2 = *(float4*)&row[8], v3 = *(float4*)&row[12];
        float mx = fmaxf(fmaxf(fmaxf(v0.x, v0.y), fmaxf(v0.z, v0.w)),
                         fmaxf(fmaxf(v1.x, v1.y), fmaxf(v1.z, v1.w)));
        mx = fmaxf(mx, fmaxf(fmaxf(fmaxf(v2.x, v2.y), fmaxf(v2.z, v2.w)),
                             fmaxf(fmaxf(v3.x, v3.y), fmaxf(v3.z, v3.w))));
        mx = fmaxf(mx, __shfl_xor_sync(~0u, mx, 1));
        mx = fmaxf(mx, __shfl_xor_sync(~0u, mx, 2));
        float e[16];
        e[0]=__expf(v0.x-mx); e[1]=__expf(v0.y-mx); e[2]=__expf(v0.z-mx); e[3]=__expf(v0.w-mx);
        e[4]=__expf(v1.x-mx); e[5]=__expf(v1.y-mx); e[6]=__expf(v1.z-mx); e[7]=__expf(v1.w-mx);
        e[8]=__expf(v2.x-mx); e[9]=__expf(v2.y-mx); e[10]=__expf(v2.z-mx); e[11]=__expf(v2.w-mx);
        e[12]=__expf(v3.x-mx); e[13]=__expf(v3.y-mx); e[14]=__expf(v3.z-mx); e[15]=__expf(v3.w-mx);
        float ssum = 0.f;
        #pragma unroll
        for (int i = 0; i < 16; i++) ssum += e[i];
        ssum += __shfl_xor_sync(~0u, ssum, 1);
        ssum += __shfl_xor_sync(~0u, ssum, 2);
        const float inv = 1.f / ssum;
        float* gattn = attn_out + (((size_t)(b * Hc + h) * Nc + r) * Nc) + s3 * 16;
        #pragma unroll
        for (int u = 0; u < 4; u++) {
            float p0 = e[4*u] * inv, p1 = e[4*u+1] * inv,
                  p2 = e[4*u+2] * inv, p3 = e[4*u+3] * inv;
            *(float4*)&gattn[4 * u] = make_float4(p0, p1, p2, p3);
            *(float4*)&row[4 * u]   = make_float4(tf32r(p0), tf32r(p1), tf32r(p2), tf32r(p3));
        }
    }
    __syncthreads();

    // ---- P5: hout[q][p] = sum_n attn[q][n] * vT[p][n] (registers) ----
    float hacc[4][4] = {};
    {
        #pragma unroll
        for (int k8 = 0; k8 < 8; k8++) {
            const int k0 = k8 * 8;
            uint32_t a[4];
            a[0] = __float_as_uint(s_S[(m0 + lr)     * 68 + k0 + lc]);
            a[1] = __float_as_uint(s_S[(m0 + lr + 8) * 68 + k0 + lc]);
            a[2] = __float_as_uint(s_S[(m0 + lr)     * 68 + k0 + lc + 4]);
            a[3] = __float_as_uint(s_S[(m0 + lr + 8) * 68 + k0 + lc + 4]);
            #pragma unroll
            for (int j = 0; j < 4; j++) {
                const int pp = (nb4 + j) * 8;
                uint32_t bfr[2];
                bfr[0] = __float_as_uint(s_vT[(pp + lr) * 68 + k0 + lc]);
                bfr[1] = __float_as_uint(s_vT[(pp + lr) * 68 + k0 + lc + 4]);
                mma16n8k8(hacc[j], a, bfr);
            }
        }
    }
    __syncthreads();   // all P5 reads of S done -> hout overlay safe

    // ---- store hout (tf32) into S region ----
    {
        #pragma unroll
        for (int j = 0; j < 4; j++) {
            const int p = (nb4 + j) * 8 + lc * 2;
            *(float2*)&s_S[(m0 + lr) * 68 + p] =
                make_float2(tf32r(hacc[j][0]), tf32r(hacc[j][1]));
            *(float2*)&s_S[(m0 + lr + 8) * 68 + p] =
                make_float2(tf32r(hacc[j][2]), tf32r(hacc[j][3]));
        }
    }
    __syncthreads();

    // ---- P6: FC partial; b-frags from g_wfcB (coalesced LDG.64); REDG ----
    {
        const int fm = (wid >> 1) * 16;      // n rows
        const int fob = (wid & 1) * 4;       // o-tile base (4 of 8)
        const float* wf = g_wfcB + (size_t)h * 4096;
        float acc[4][4] = {};
        #pragma unroll
        for (int k8 = 0; k8 < 8; k8++) {
            const int k0 = k8 * 8;
            uint32_t a[4];
            a[0] = __float_as_uint(s_S[(fm + lr)     * 68 + k0 + lc]);
            a[1] = __float_as_uint(s_S[(fm + lr + 8) * 68 + k0 + lc]);
            a[2] = __float_as_uint(s_S[(fm + lr)     * 68 + k0 + lc + 4]);
            a[3] = __float_as_uint(s_S[(fm + lr + 8) * 68 + k0 + lc + 4]);
            #pragma unroll
            for (int t = 0; t < 4; t++) {
                float2 w = *(const float2*)&wf[(k8 * 8 + fob + t) * 64 + lane * 2];
                uint32_t bfr[2] = { __float_as_uint(w.x), __float_as_uint(w.y) };
                mma16n8k8(acc[t], a, bfr);
            }
        }
        float* ob = out + (size_t)b * 4096;
        #pragma unroll
        for (int t = 0; t < 4; t++) {
            const int o = (fob + t) * 8 + lc * 2;
            redg_add(ob + (fm + lr) * 64 + o,     acc[t][0]);
            redg_add(ob + (fm + lr) * 64 + o + 1, acc[t][1]);
            redg_add(ob + (fm + lr + 8) * 64 + o,     acc[t][2]);
            redg_add(ob + (fm + lr + 8) * 64 + o + 1, acc[t][3]);
        }
    }
}

// ---------------------------------------------------------------------------
extern "C" void kernel_launch(void* const* d_in, const int* in_sizes, int n_in,
                              void* d_out, int out_size) {
    const float* feat  = (const float*)d_in[0];
    const int*   sidx  = (const int*)  d_in[1];
    const float* gamma = (const float*)d_in[2];
    const float* beta  = (const float*)d_in[3];
    const float* Wq    = (const float*)d_in[4];
    const float* Wk    = (const float*)d_in[5];
    const float* Wv1   = (const float*)d_in[6];
    const float* Wv2   = (const float*)d_in[7];
    const float* Wfc   = (const float*)d_in[8];

    float* out  = (float*)d_out;
    float* attn = out + (size_t)Bc * Nc * 64;

    cudaFuncSetAttribute(ln_y_kernel, cudaFuncAttributeMaxDynamicSharedMemorySize, SMEMY);
    cudaFuncSetAttribute(head_mma,    cudaFuncAttributeMaxDynamicSharedMemorySize, SMEM2);

    pack_w<<<Hc, 256>>>(Wq, Wk, Wfc);
    ln_y_kernel<<<Bc, 256, SMEMY>>>(feat, gamma, beta, out);
    head_mma<<<dim3(Bc, Hc), 256, SMEM2>>>(feat, sidx, Wv1, Wv2, out, attn);
}

// round 14
// speedup vs baseline: 1.6723x; 1.0062x over previous
#include <cuda_runtime.h>
#include <math.h>
#include <stdint.h>

#define Bc 512
#define Mc 4096
#define Nc 64
#define Hc 8

// Scratch (device globals, allocation-free rule)
__device__ float g_y[(size_t)Bc * Mc];       // 8 MB, LN'd features (tf32, affine)
__device__ float g_wqB[Hc * 8 * 4 * 64];     // q-GEMM B frags  [h][k8][t4][lane*2]
__device__ float g_wkA[Hc * 8 * 2 * 128];    // key-GEMM A frags [h][k8][mt2][lane*4]
__device__ float g_wfcB[Hc * 8 * 8 * 64];    // FC B frags      [h][k8][ot8][lane*2]

__device__ __forceinline__ float tf32r(float x) {
    float r; asm("cvt.rna.tf32.f32 %0, %1;" : "=f"(r) : "f"(x)); return r;
}
__device__ __forceinline__ void mma16n8k8(float* c, const uint32_t* a, const uint32_t* b) {
    asm volatile(
        "mma.sync.aligned.m16n8k8.row.col.f32.tf32.tf32.f32 "
        "{%0,%1,%2,%3}, {%4,%5,%6,%7}, {%8,%9}, {%0,%1,%2,%3};"
        : "+f"(c[0]), "+f"(c[1]), "+f"(c[2]), "+f"(c[3])
        : "r"(a[0]), "r"(a[1]), "r"(a[2]), "r"(a[3]), "r"(b[0]), "r"(b[1]));
}
__device__ __forceinline__ uint32_t smem_u32(const void* p) {
    uint32_t a;
    asm("{ .reg .u64 t; cvta.to.shared.u64 t, %1; cvt.u32.u64 %0, t; }" : "=r"(a) : "l"(p));
    return a;
}
__device__ __forceinline__ void cp16(uint32_t s, const void* g) {
    asm volatile("cp.async.cg.shared.global [%0], [%1], 16;" :: "r"(s), "l"(g));
}
__device__ __forceinline__ void redg_add(float* g, float v) {
    asm volatile("red.global.add.f32 [%0], %1;" :: "l"(g), "f"(v) : "memory");
}
#define CP_COMMIT()  asm volatile("cp.async.commit_group;" ::: "memory")
#define CP_WAIT(n)   asm volatile("cp.async.wait_group %0;" :: "n"(n) : "memory")
#define BAR_SYNC(id, cnt) asm volatile("bar.sync %0, %1;" :: "r"(id), "r"(cnt) : "memory")

// ---------------------------------------------------------------------------
// Kernel 0: LayerNorm -> g_y (tf32, affine), zero out[b] row, AND (blocks 0..7)
// pack weights for head h = blockIdx.x into fragment-order arrays. grid=B.
// ---------------------------------------------------------------------------
static constexpr int SMEMY = 4096 * 4 + 80;

__global__ __launch_bounds__(256) void ln_y_kernel(
    const float* __restrict__ feat, const float* __restrict__ gamma,
    const float* __restrict__ beta, const float* __restrict__ Wq,
    const float* __restrict__ Wk, const float* __restrict__ Wfc,
    float* __restrict__ out)
{
    extern __shared__ float sm[];
    float* s_x = sm;
    float* s_red = sm + 4096;

    const int b = blockIdx.x, tid = threadIdx.x;
    const int wid = tid >> 5, lane = tid & 31;
    const float4* x4 = (const float4*)(feat + (size_t)b * Mc);

    {   // zero this batch's out row (head REDG-accumulates into it)
        float4* o4 = (float4*)(out + (size_t)b * 4096);
        #pragma unroll
        for (int j = 0; j < 4; j++)
            o4[tid + j * 256] = make_float4(0.f, 0.f, 0.f, 0.f);
    }

    float sum = 0.f, sq = 0.f;
    for (int i = tid; i < 1024; i += 256) {
        float4 v = x4[i];
        *(float4*)&s_x[i * 4] = v;
        sum += v.x + v.y + v.z + v.w;
        sq  += v.x*v.x + v.y*v.y + v.z*v.z + v.w*v.w;
    }
    #pragma unroll
    for (int o = 16; o; o >>= 1) {
        sum += __shfl_xor_sync(~0u, sum, o);
        sq  += __shfl_xor_sync(~0u, sq,  o);
    }
    if (lane == 0) { s_red[wid] = sum; s_red[wid + 8] = sq; }
    __syncthreads();
    if (tid == 0) {
        float S = 0.f, Q = 0.f;
        #pragma unroll
        for (int i = 0; i < 8; i++) { S += s_red[i]; Q += s_red[i + 8]; }
        float mu = S * (1.f / Mc);
        s_red[16] = mu;
        s_red[17] = rsqrtf(Q * (1.f / Mc) - mu * mu + 1e-5f);
    }
    __syncthreads();
    const float mu = s_red[16], rstd = s_red[17];
    float4* y4 = (float4*)(g_y + (size_t)b * Mc);
    const float4* g4 = (const float4*)gamma;
    const float4* b4 = (const float4*)beta;
    for (int i = tid; i < 1024; i += 256) {
        float4 v = *(float4*)&s_x[i * 4];
        float4 g = g4[i], bb = b4[i], y;
        y.x = tf32r((v.x - mu) * rstd * g.x + bb.x);
        y.y = tf32r((v.y - mu) * rstd * g.y + bb.y);
        y.z = tf32r((v.z - mu) * rstd * g.z + bb.z);
        y.w = tf32r((v.w - mu) * rstd * g.w + bb.w);
        y4[i] = y;
    }

    // ---- blocks 0..7: pack weights for head h = b ----
    if (b < Hc) {
        const int h = b;
        for (int i = tid; i < 1024; i += 256) {
            int k8 = i >> 7, t = (i >> 5) & 3, ln2 = i & 31;
            int plr = ln2 >> 2, plc = ln2 & 3;
            const float* src = Wq + (size_t)(h * 32 + t * 8 + plr) * 64 + k8 * 8 + plc;
            *(float2*)&g_wqB[(size_t)h * 2048 + i * 2] =
                make_float2(tf32r(src[0]), tf32r(src[4]));
        }
        for (int i = tid; i < 512; i += 256) {
            int k8 = i >> 6, mt = (i >> 5) & 1, ln2 = i & 31;
            int plr = ln2 >> 2, plc = ln2 & 3;
            const float* src = Wk + (size_t)h * 2048 + (mt * 16 + plr) * 64 + k8 * 8 + plc;
            *(float4*)&g_wkA[(size_t)h * 2048 + i * 4] =
                make_float4(tf32r(src[0]), tf32r(src[8 * 64]),
                            tf32r(src[4]), tf32r(src[8 * 64 + 4]));
        }
        for (int i = tid; i < 2048; i += 256) {
            int k8 = i >> 8, ot = (i >> 5) & 7, ln2 = i & 31;
            int plr = ln2 >> 2, plc = ln2 & 3;
            const float* src = Wfc + (size_t)(ot * 8 + plr) * 512 + h * 64 + k8 * 8 + plc;
            *(float2*)&g_wfcB[(size_t)h * 4096 + i * 2] =
                make_float2(tf32r(src[0]), tf32r(src[4]));
        }
    }
}

// ---------------------------------------------------------------------------
// Kernel 1: per-(b,h) head; weights via packed coalesced global frags (L1).
// Warp-specialized A/B phases. smem:
//   @0     kf[64][68]  — gathered feats; S overlay; hout overlay
//   @4352  feat[4096]  — raw feats; vT overlay in phase B
//   @8704  y[64][68]   — dies after q GEMM; then keyT[64][36]@8704 + q@11008
//   @13312 wv[16]
// total 13328 floats = 53.3 KB -> 4 CTA/SM.
// ---------------------------------------------------------------------------
static constexpr int SMEM2 = 13328 * 4;

__global__ __launch_bounds__(256, 4) void head_mma(
    const float* __restrict__ feat, const int* __restrict__ sidx,
    const float* __restrict__ Wv1, const float* __restrict__ Wv2,
    float* __restrict__ out, float* __restrict__ attn_out)
{
    extern __shared__ float sm[];
    float* s_kf   = sm;            // [64][68]
    float* s_S    = sm;            // overlay
    float* s_vT   = sm + 4352;     // [p][n] pitch 68
    float* s_feat = sm + 4352;
    float* s_y    = sm + 8704;     // dies after q GEMM
    float* s_keyT = sm + 8704;     // [n][d] pitch 36
    float* s_q    = sm + 11008;    // [q][d] pitch 36
    float* s_wv   = sm + 13312;    // wv1[12], wv2[4]

    const int b = blockIdx.x, h = blockIdx.y, tid = threadIdx.x;
    const int wid = tid >> 5, lane = tid & 31;
    const int lr = lane >> 2, lc = lane & 3;
    const int* idx = sidx + (size_t)h * Mc;
    const uint32_t sbase = smem_u32(sm);

    float qacc[4][4] = {};

    // ======================= PHASE A (warp-specialized) =======================
    if (wid < 4) {
        const int t4 = tid;                      // 0..127
        const float* yg = g_y + (size_t)b * Mc;
        #pragma unroll
        for (int j = 0; j < 8; j++) {
            int i = t4 + j * 128;                // 0..1023
            int n = i >> 4, k4 = i & 15;
            cp16(sbase + (uint32_t)(8704 + n * 68 + k4 * 4) * 4, yg + i * 4);
        }
        CP_COMMIT();
        CP_WAIT(0);
        BAR_SYNC(1, 128);

        // ---- q GEMM: rows qm=wid*16; b-frags from g_wqB (coalesced LDG.64) ----
        const int qm = wid * 16;
        const float* wq = g_wqB + (size_t)h * 2048;
        #pragma unroll
        for (int k8 = 0; k8 < 8; k8++) {
            const int k0 = k8 * 8;
            uint32_t a[4];
            a[0] = __float_as_uint(s_y[(qm + lr)     * 68 + k0 + lc]);
            a[1] = __float_as_uint(s_y[(qm + lr + 8) * 68 + k0 + lc]);
            a[2] = __float_as_uint(s_y[(qm + lr)     * 68 + k0 + lc + 4]);
            a[3] = __float_as_uint(s_y[(qm + lr + 8) * 68 + k0 + lc + 4]);
            #pragma unroll
            for (int t = 0; t < 4; t++) {
                float2 w = *(const float2*)&wq[(k8 * 4 + t) * 64 + lane * 2];
                uint32_t bfr[2] = { __float_as_uint(w.x), __float_as_uint(w.y) };
                mma16n8k8(qacc[t], a, bfr);
            }
        }
    } else {
        const int t4 = tid - 128;                // 0..127
        const float* xg = feat + (size_t)b * Mc;
        #pragma unroll
        for (int j = 0; j < 8; j++) {
            int i = t4 + j * 128;
            cp16(sbase + (uint32_t)(4352 + i * 4) * 4, xg + i * 4);
        }
        CP_COMMIT();
        if (t4 < 12) s_wv[t4] = Wv1[h * 12 + t4];
        if (t4 >= 32 && t4 < 36) s_wv[12 + t4 - 32] = Wv2[h * 4 + t4 - 32];
        CP_WAIT(0);
        BAR_SYNC(2, 128);

        // ---- gather kf from smem feat; zero conv pad ----
        const int4* idx4 = (const int4*)idx;
        #pragma unroll
        for (int j = 0; j < 8; j++) {
            int i = t4 + j * 128;                // 0..1023
            int4 v = idx4[i];
            int n = i >> 4, k = (i & 15) * 4;
            float4 g = make_float4(s_feat[v.x], s_feat[v.y], s_feat[v.z], s_feat[v.w]);
            *(float4*)&s_kf[n * 68 + k] = g;
        }
        s_kf[(t4 >> 1) * 68 + 64 + (t4 & 1)] = 0.f;
    }
    __syncthreads();   // kf, y, wv visible CTA-wide

    // ======================= PHASE B (warp-specialized) =======================
    if (wid < 4) {
        // ---- q frag store (x 1/64) ----
        const int qm = wid * 16;
        #pragma unroll
        for (int t = 0; t < 4; t++) {
            const int d = t * 8 + lc * 2;
            s_q[(qm + lr) * 36 + d]         = tf32r(qacc[t][0] * 0.015625f);
            s_q[(qm + lr) * 36 + d + 1]     = tf32r(qacc[t][1] * 0.015625f);
            s_q[(qm + lr + 8) * 36 + d]     = tf32r(qacc[t][2] * 0.015625f);
            s_q[(qm + lr + 8) * 36 + d + 1] = tf32r(qacc[t][3] * 0.015625f);
        }
        // ---- key GEMM: a-frags from g_wkA (coalesced LDG.128) ----
        const int mt = wid & 1;
        const int m0 = mt * 16;
        const int nb = (wid >> 1) * 8;
        const float* wk = g_wkA + (size_t)h * 2048;
        float acc[4][4] = {};
        #pragma unroll
        for (int k8 = 0; k8 < 8; k8++) {
            const int k0 = k8 * 8;
            float4 w = *(const float4*)&wk[(k8 * 2 + mt) * 128 + lane * 4];
            uint32_t a[4] = { __float_as_uint(w.x), __float_as_uint(w.y),
                              __float_as_uint(w.z), __float_as_uint(w.w) };
            #pragma unroll
            for (int t = 0; t < 4; t++) {
                const int nn = nb + t * 16;
                uint32_t bfr[2];
                bfr[0] = __float_as_uint(tf32r(s_kf[(nn + lr) * 68 + k0 + lc]));
                bfr[1] = __float_as_uint(tf32r(s_kf[(nn + lr) * 68 + k0 + lc + 4]));
                mma16n8k8(acc[t], a, bfr);
            }
        }
        #pragma unroll
        for (int t = 0; t < 4; t++) {
            const int n = nb + t * 16 + lc * 2, d = m0 + lr;
            s_keyT[n * 36 + d]           = tf32r(acc[t][0]);
            s_keyT[(n + 1) * 36 + d]     = tf32r(acc[t][1]);
            s_keyT[n * 36 + d + 8]       = tf32r(acc[t][2]);
            s_keyT[(n + 1) * 36 + d + 8] = tf32r(acc[t][3]);
        }
    } else {
        // ---- conv (128 threads): n = t4>>1, p0 = (t4&1)*32 ----
        const int t4 = tid - 128;
        const int n = t4 >> 1, p0 = (t4 & 1) * 32;
        const float* kr = s_kf + n * 68;
        float w0[4], w1[4], w2[4], w3[4];
        #pragma unroll
        for (int d = 0; d < 4; d++) {
            w0[d] = s_wv[d * 3]; w1[d] = s_wv[d * 3 + 1];
            w2[d] = s_wv[d * 3 + 2]; w3[d] = s_wv[12 + d];
        }
        float x0 = kr[p0], x1 = kr[p0 + 1];
        #pragma unroll
        for (int i = 0; i < 32; i++) {
            float x2 = kr[p0 + i + 2];
            float acc = x0;
            #pragma unroll
            for (int d = 0; d < 4; d++)
                acc += fmaxf(x0 * w0[d] + x1 * w1[d] + x2 * w2[d], 0.f) * w3[d];
            s_vT[(p0 + i) * 68 + n] = tf32r(acc);
            x0 = x1; x1 = x2;
        }
    }
    __syncthreads();

    const int m0 = (wid >> 1) * 16;       // q tile
    const int nb4 = (wid & 1) * 4;        // 4 n-tiles

    // ---- P3: S[q][n] = sum_d q[q][d] * keyT[n][d] -> S overlay (kf dead) ----
    {
        float acc[4][4] = {};
        #pragma unroll
        for (int k8 = 0; k8 < 4; k8++) {
            const int k0 = k8 * 8;
            uint32_t a[4];
            a[0] = __float_as_uint(s_q[(m0 + lr)     * 36 + k0 + lc]);
            a[1] = __float_as_uint(s_q[(m0 + lr + 8) * 36 + k0 + lc]);
            a[2] = __float_as_uint(s_q[(m0 + lr)     * 36 + k0 + lc + 4]);
            a[3] = __float_as_uint(s_q[(m0 + lr + 8) * 36 + k0 + lc + 4]);
            #pragma unroll
            for (int j = 0; j < 4; j++) {
                const int nn = (nb4 + j) * 8;
                uint32_t bfr[2];
                bfr[0] = __float_as_uint(s_keyT[(nn + lr) * 36 + k0 + lc]);
                bfr[1] = __float_as_uint(s_keyT[(nn + lr) * 36 + k0 + lc + 4]);
                mma16n8k8(acc[j], a, bfr);
            }
        }
        #pragma unroll
        for (int j = 0; j < 4; j++) {
            const int col = (nb4 + j) * 8 + lc * 2;
            *(float2*)&s_S[(m0 + lr)     * 68 + col] = make_float2(acc[j][0], acc[j][1]);
            *(float2*)&s_S[(m0 + lr + 8) * 68 + col] = make_float2(acc[j][2], acc[j][3]);
        }
    }
    __syncthreads();

    // ---- P4: softmax rows of S; global attn fp32, smem tf32 ----
    {
        const int r = tid >> 2, s3 = tid & 3;
        float* row = s_S + r * 68 + s3 * 16;
        float4 v0 = *(float4*)&row[0], v1 = *(float4*)&row[4];
        float4 v2 = *(float4*)&row[8], v3 = *(float4*)&row[12];
        float mx = fmaxf(fmaxf(fmaxf(v0.x, v0.y), fmaxf(v0.z, v0.w)),
                         fmaxf(fmaxf(v1.x, v1.y), fmaxf(v1.z, v1.w)));
        mx = fmaxf(mx, fmaxf(fmaxf(fmaxf(v2.x, v2.y), fmaxf(v2.z, v2.w)),
                             fmaxf(fmaxf(v3.x, v3.y), fmaxf(v3.z, v3.w))));
        mx = fmaxf(mx, __shfl_xor_sync(~0u, mx, 1));
        mx = fmaxf(mx, __shfl_xor_sync(~0u, mx, 2));
        float e[16];
        e[0]=__expf(v0.x-mx); e[1]=__expf(v0.y-mx); e[2]=__expf(v0.z-mx); e[3]=__expf(v0.w-mx);
        e[4]=__expf(v1.x-mx); e[5]=__expf(v1.y-mx); e[6]=__expf(v1.z-mx); e[7]=__expf(v1.w-mx);
        e[8]=__expf(v2.x-mx); e[9]=__expf(v2.y-mx); e[10]=__expf(v2.z-mx); e[11]=__expf(v2.w-mx);
        e[12]=__expf(v3.x-mx); e[13]=__expf(v3.y-mx); e[14]=__expf(v3.z-mx); e[15]=__expf(v3.w-mx);
        float ssum = 0.f;
        #pragma unroll
        for (int i = 0; i < 16; i++) ssum += e[i];
        ssum += __shfl_xor_sync(~0u, ssum, 1);
        ssum += __shfl_xor_sync(~0u, ssum, 2);
        const float inv = 1.f / ssum;
        float* gattn = attn_out + (((size_t)(b * Hc + h) * Nc + r) * Nc) + s3 * 16;
        #pragma unroll
        for (int u = 0; u < 4; u++) {
            float p0 = e[4*u] * inv, p1 = e[4*u+1] * inv,
                  p2 = e[4*u+2] * inv, p3 = e[4*u+3] * inv;
            *(float4*)&gattn[4 * u] = make_float4(p0, p1, p2, p3);
            *(float4*)&row[4 * u]   = make_float4(tf32r(p0), tf32r(p1), tf32r(p2), tf32r(p3));
        }
    }
    __syncthreads();

    // ---- P5: hout[q][p] = sum_n attn[q][n] * vT[p][n] (registers) ----
    float hacc[4][4] = {};
    {
        #pragma unroll
        for (int k8 = 0; k8 < 8; k8++) {
            const int k0 = k8 * 8;
            uint32_t a[4];
            a[0] = __float_as_uint(s_S[(m0 + lr)     * 68 + k0 + lc]);
            a[1] = __float_as_uint(s_S[(m0 + lr + 8) * 68 + k0 + lc]);
            a[2] = __float_as_uint(s_S[(m0 + lr)     * 68 + k0 + lc + 4]);
            a[3] = __float_as_uint(s_S[(m0 + lr + 8) * 68 + k0 + lc + 4]);
            #pragma unroll
            for (int j = 0; j < 4; j++) {
                const int pp = (nb4 + j) * 8;
                uint32_t bfr[2];
                bfr[0] = __float_as_uint(s_vT[(pp + lr) * 68 + k0 + lc]);
                bfr[1] = __float_as_uint(s_vT[(pp + lr) * 68 + k0 + lc + 4]);
                mma16n8k8(hacc[j], a, bfr);
            }
        }
    }
    __syncthreads();   // all P5 reads of S done -> hout overlay safe

    // ---- store hout (tf32) into S region ----
    {
        #pragma unroll
        for (int j = 0; j < 4; j++) {
            const int p = (nb4 + j) * 8 + lc * 2;
            *(float2*)&s_S[(m0 + lr) * 68 + p] =
                make_float2(tf32r(hacc[j][0]), tf32r(hacc[j][1]));
            *(float2*)&s_S[(m0 + lr + 8) * 68 + p] =
                make_float2(tf32r(hacc[j][2]), tf32r(hacc[j][3]));
        }
    }
    __syncthreads();

    // ---- P6: FC partial; b-frags from g_wfcB (coalesced LDG.64); REDG ----
    {
        const int fm = (wid >> 1) * 16;      // n rows
        const int fob = (wid & 1) * 4;       // o-tile base (4 of 8)
        const float* wf = g_wfcB + (size_t)h * 4096;
        float acc[4][4] = {};
        #pragma unroll
        for (int k8 = 0; k8 < 8; k8++) {
            const int k0 = k8 * 8;
            uint32_t a[4];
            a[0] = __float_as_uint(s_S[(fm + lr)     * 68 + k0 + lc]);
            a[1] = __float_as_uint(s_S[(fm + lr + 8) * 68 + k0 + lc]);
            a[2] = __float_as_uint(s_S[(fm + lr)     * 68 + k0 + lc + 4]);
            a[3] = __float_as_uint(s_S[(fm + lr + 8) * 68 + k0 + lc + 4]);
            #pragma unroll
            for (int t = 0; t < 4; t++) {
                float2 w = *(const float2*)&wf[(k8 * 8 + fob + t) * 64 + lane * 2];
                uint32_t bfr[2] = { __float_as_uint(w.x), __float_as_uint(w.y) };
                mma16n8k8(acc[t], a, bfr);
            }
        }
        float* ob = out + (size_t)b * 4096;
        #pragma unroll
        for (int t = 0; t < 4; t++) {
            const int o = (fob + t) * 8 + lc * 2;
            redg_add(ob + (fm + lr) * 64 + o,     acc[t][0]);
            redg_add(ob + (fm + lr) * 64 + o + 1, acc[t][1]);
            redg_add(ob + (fm + lr + 8) * 64 + o,     acc[t][2]);
            redg_add(ob + (fm + lr + 8) * 64 + o + 1, acc[t][3]);
        }
    }
}

// ---------------------------------------------------------------------------
extern "C" void kernel_launch(void* const* d_in, const int* in_sizes, int n_in,
                              void* d_out, int out_size) {
    const float* feat  = (const float*)d_in[0];
    const int*   sidx  = (const int*)  d_in[1];
    const float* gamma = (const float*)d_in[2];
    const float* beta  = (const float*)d_in[3];
    const float* Wq    = (const float*)d_in[4];
    const float* Wk    = (const float*)d_in[5];
    const float* Wv1   = (const float*)d_in[6];
    const float* Wv2   = (const float*)d_in[7];
    const float* Wfc   = (const float*)d_in[8];

    float* out  = (float*)d_out;
    float* attn = out + (size_t)Bc * Nc * 64;

    cudaFuncSetAttribute(ln_y_kernel, cudaFuncAttributeMaxDynamicSharedMemorySize, SMEMY);
    cudaFuncSetAttribute(head_mma,    cudaFuncAttributeMaxDynamicSharedMemorySize, SMEM2);

    ln_y_kernel<<<Bc, 256, SMEMY>>>(feat, gamma, beta, Wq, Wk, Wfc, out);
    head_mma<<<dim3(Bc, Hc), 256, SMEM2>>>(feat, sidx, Wv1, Wv2, out, attn);
}

// round 15
// speedup vs baseline: 1.6920x; 1.0118x over previous
#include <cuda_runtime.h>
#include <math.h>
#include <stdint.h>

#define Bc 512
#define Mc 4096
#define Nc 64
#define Hc 8

// Scratch (device globals, allocation-free rule)
__device__ float g_y[(size_t)Bc * Mc];       // 8 MB, LN'd feats, q-GEMM FRAGMENT ORDER
__device__ float g_wqB[Hc * 8 * 4 * 64];     // q-GEMM B frags  [h][k8][t4][lane*2]
__device__ float g_wkA[Hc * 8 * 2 * 128];    // key-GEMM A frags [h][k8][mt2][lane*4]
__device__ float g_wfcB[Hc * 8 * 8 * 64];    // FC B frags      [h][k8][ot8][lane*2]

__device__ __forceinline__ float tf32r(float x) {
    float r; asm("cvt.rna.tf32.f32 %0, %1;" : "=f"(r) : "f"(x)); return r;
}
__device__ __forceinline__ void mma16n8k8(float* c, const uint32_t* a, const uint32_t* b) {
    asm volatile(
        "mma.sync.aligned.m16n8k8.row.col.f32.tf32.tf32.f32 "
        "{%0,%1,%2,%3}, {%4,%5,%6,%7}, {%8,%9}, {%0,%1,%2,%3};"
        : "+f"(c[0]), "+f"(c[1]), "+f"(c[2]), "+f"(c[3])
        : "r"(a[0]), "r"(a[1]), "r"(a[2]), "r"(a[3]), "r"(b[0]), "r"(b[1]));
}
__device__ __forceinline__ uint32_t smem_u32(const void* p) {
    uint32_t a;
    asm("{ .reg .u64 t; cvta.to.shared.u64 t, %1; cvt.u32.u64 %0, t; }" : "=r"(a) : "l"(p));
    return a;
}
__device__ __forceinline__ void cp16(uint32_t s, const void* g) {
    asm volatile("cp.async.cg.shared.global [%0], [%1], 16;" :: "r"(s), "l"(g));
}
__device__ __forceinline__ void redg_add(float* g, float v) {
    asm volatile("red.global.add.f32 [%0], %1;" :: "l"(g), "f"(v) : "memory");
}
#define CP_COMMIT()  asm volatile("cp.async.commit_group;" ::: "memory")
#define CP_WAIT(n)   asm volatile("cp.async.wait_group %0;" :: "n"(n) : "memory")
#define BAR_SYNC(id, cnt) asm volatile("bar.sync %0, %1;" :: "r"(id), "r"(cnt) : "memory")

// ---------------------------------------------------------------------------
// Kernel 0: LayerNorm -> g_y (tf32, affine, FRAGMENT-PACKED), zero out[b] row,
// AND (blocks 0..7) pack weights for head h = blockIdx.x. grid=B.
// ---------------------------------------------------------------------------
static constexpr int SMEMY = 4096 * 4 + 80;

__global__ __launch_bounds__(256) void ln_y_kernel(
    const float* __restrict__ feat, const float* __restrict__ gamma,
    const float* __restrict__ beta, const float* __restrict__ Wq,
    const float* __restrict__ Wk, const float* __restrict__ Wfc,
    float* __restrict__ out)
{
    extern __shared__ float sm[];
    float* s_x = sm;
    float* s_red = sm + 4096;

    const int b = blockIdx.x, tid = threadIdx.x;
    const int wid = tid >> 5, lane = tid & 31;
    const float4* x4 = (const float4*)(feat + (size_t)b * Mc);

    {   // zero this batch's out row (head REDG-accumulates into it)
        float4* o4 = (float4*)(out + (size_t)b * 4096);
        #pragma unroll
        for (int j = 0; j < 4; j++)
            o4[tid + j * 256] = make_float4(0.f, 0.f, 0.f, 0.f);
    }

    float sum = 0.f, sq = 0.f;
    for (int i = tid; i < 1024; i += 256) {
        float4 v = x4[i];
        *(float4*)&s_x[i * 4] = v;
        sum += v.x + v.y + v.z + v.w;
        sq  += v.x*v.x + v.y*v.y + v.z*v.z + v.w*v.w;
    }
    #pragma unroll
    for (int o = 16; o; o >>= 1) {
        sum += __shfl_xor_sync(~0u, sum, o);
        sq  += __shfl_xor_sync(~0u, sq,  o);
    }
    if (lane == 0) { s_red[wid] = sum; s_red[wid + 8] = sq; }
    __syncthreads();
    if (tid == 0) {
        float S = 0.f, Q = 0.f;
        #pragma unroll
        for (int i = 0; i < 8; i++) { S += s_red[i]; Q += s_red[i + 8]; }
        float mu = S * (1.f / Mc);
        s_red[16] = mu;
        s_red[17] = rsqrtf(Q * (1.f / Mc) - mu * mu + 1e-5f);
    }
    __syncthreads();
    const float mu = s_red[16], rstd = s_red[17];
    const float4* g4 = (const float4*)gamma;
    const float4* b4 = (const float4*)beta;
    // affine in-place (tf32-rounded)
    for (int i = tid; i < 1024; i += 256) {
        float4 v = *(float4*)&s_x[i * 4];
        float4 g = g4[i], bb = b4[i];
        v.x = tf32r((v.x - mu) * rstd * g.x + bb.x);
        v.y = tf32r((v.y - mu) * rstd * g.y + bb.y);
        v.z = tf32r((v.z - mu) * rstd * g.z + bb.z);
        v.w = tf32r((v.w - mu) * rstd * g.w + bb.w);
        *(float4*)&s_x[i * 4] = v;
    }
    __syncthreads();
    // packed fragment write: i = (k8*4 + t)*32 + lane2 ; 4 values per lane
    for (int i = tid; i < 1024; i += 256) {
        int lane2 = i & 31, t = (i >> 5) & 3, k8 = i >> 7;
        int plr = lane2 >> 2, plc = lane2 & 3;
        int row = t * 16 + plr, col = k8 * 8 + plc;
        float4 v;
        v.x = s_x[row * 64 + col];
        v.y = s_x[(row + 8) * 64 + col];
        v.z = s_x[row * 64 + col + 4];
        v.w = s_x[(row + 8) * 64 + col + 4];
        *(float4*)&g_y[(size_t)b * 4096 + i * 4] = v;
    }

    // ---- blocks 0..7: pack weights for head h = b ----
    if (b < Hc) {
        const int h = b;
        for (int i = tid; i < 1024; i += 256) {
            int k8 = i >> 7, t = (i >> 5) & 3, ln2 = i & 31;
            int plr = ln2 >> 2, plc = ln2 & 3;
            const float* src = Wq + (size_t)(h * 32 + t * 8 + plr) * 64 + k8 * 8 + plc;
            *(float2*)&g_wqB[(size_t)h * 2048 + i * 2] =
                make_float2(tf32r(src[0]), tf32r(src[4]));
        }
        for (int i = tid; i < 512; i += 256) {
            int k8 = i >> 6, mt = (i >> 5) & 1, ln2 = i & 31;
            int plr = ln2 >> 2, plc = ln2 & 3;
            const float* src = Wk + (size_t)h * 2048 + (mt * 16 + plr) * 64 + k8 * 8 + plc;
            *(float4*)&g_wkA[(size_t)h * 2048 + i * 4] =
                make_float4(tf32r(src[0]), tf32r(src[8 * 64]),
                            tf32r(src[4]), tf32r(src[8 * 64 + 4]));
        }
        for (int i = tid; i < 2048; i += 256) {
            int k8 = i >> 8, ot = (i >> 5) & 7, ln2 = i & 31;
            int plr = ln2 >> 2, plc = ln2 & 3;
            const float* src = Wfc + (size_t)(ot * 8 + plr) * 512 + h * 64 + k8 * 8 + plc;
            *(float2*)&g_wfcB[(size_t)h * 4096 + i * 2] =
                make_float2(tf32r(src[0]), tf32r(src[4]));
        }
    }
}

// ---------------------------------------------------------------------------
// Kernel 1: per-(b,h) head; all GEMM operands either smem-frag-clean or
// packed-coalesced global. Warp-specialized A/B phases. smem:
//   @0     kf[64][68]  — gathered feats; S overlay; hout overlay
//   @4352  feat[4096]  — raw feats; vT overlay in phase B
//   @8704  keyT[64][36] + q[64][36]@11008 (standalone region)
//   @13312 wv[16]
// total 13328 floats = 53.3 KB -> 4 CTA/SM.
// ---------------------------------------------------------------------------
static constexpr int SMEM2 = 13328 * 4;

__global__ __launch_bounds__(256, 4) void head_mma(
    const float* __restrict__ feat, const int* __restrict__ sidx,
    const float* __restrict__ Wv1, const float* __restrict__ Wv2,
    float* __restrict__ out, float* __restrict__ attn_out)
{
    extern __shared__ float sm[];
    float* s_kf   = sm;            // [64][68]
    float* s_S    = sm;            // overlay
    float* s_vT   = sm + 4352;     // [p][n] pitch 68
    float* s_feat = sm + 4352;
    float* s_keyT = sm + 8704;     // [n][d] pitch 36
    float* s_q    = sm + 11008;    // [q][d] pitch 36
    float* s_wv   = sm + 13312;    // wv1[12], wv2[4]

    const int b = blockIdx.x, h = blockIdx.y, tid = threadIdx.x;
    const int wid = tid >> 5, lane = tid & 31;
    const int lr = lane >> 2, lc = lane & 3;
    const int* idx = sidx + (size_t)h * Mc;
    const uint32_t sbase = smem_u32(sm);

    // ======================= PHASE A (warp-specialized) =======================
    if (wid < 4) {
        // ---- q GEMM entirely from global packed frags (no staging, no wait) ----
        const float* yb = g_y + (size_t)b * 4096;     // fragment-packed
        const float* wq = g_wqB + (size_t)h * 2048;
        float qacc[4][4] = {};
        #pragma unroll
        for (int k8 = 0; k8 < 8; k8++) {
            float4 av = *(const float4*)&yb[(k8 * 4 + wid) * 128 + lane * 4];
            uint32_t a[4] = { __float_as_uint(av.x), __float_as_uint(av.y),
                              __float_as_uint(av.z), __float_as_uint(av.w) };
            #pragma unroll
            for (int t = 0; t < 4; t++) {
                float2 w = *(const float2*)&wq[(k8 * 4 + t) * 64 + lane * 2];
                uint32_t bfr[2] = { __float_as_uint(w.x), __float_as_uint(w.y) };
                mma16n8k8(qacc[t], a, bfr);
            }
        }
        // ---- q frag store (x 1/64) to standalone region (no hazard) ----
        const int qm = wid * 16;
        #pragma unroll
        for (int t = 0; t < 4; t++) {
            const int d = t * 8 + lc * 2;
            s_q[(qm + lr) * 36 + d]         = tf32r(qacc[t][0] * 0.015625f);
            s_q[(qm + lr) * 36 + d + 1]     = tf32r(qacc[t][1] * 0.015625f);
            s_q[(qm + lr + 8) * 36 + d]     = tf32r(qacc[t][2] * 0.015625f);
            s_q[(qm + lr + 8) * 36 + d + 1] = tf32r(qacc[t][3] * 0.015625f);
        }
    } else {
        const int t4 = tid - 128;                // 0..127
        const float* xg = feat + (size_t)b * Mc;
        #pragma unroll
        for (int j = 0; j < 8; j++) {
            int i = t4 + j * 128;
            cp16(sbase + (uint32_t)(4352 + i * 4) * 4, xg + i * 4);
        }
        CP_COMMIT();
        if (t4 < 12) s_wv[t4] = Wv1[h * 12 + t4];
        if (t4 >= 32 && t4 < 36) s_wv[12 + t4 - 32] = Wv2[h * 4 + t4 - 32];
        CP_WAIT(0);
        BAR_SYNC(2, 128);

        // ---- gather kf from smem feat; zero conv pad ----
        const int4* idx4 = (const int4*)idx;
        #pragma unroll
        for (int j = 0; j < 8; j++) {
            int i = t4 + j * 128;                // 0..1023
            int4 v = idx4[i];
            int n = i >> 4, k = (i & 15) * 4;
            float4 g = make_float4(s_feat[v.x], s_feat[v.y], s_feat[v.z], s_feat[v.w]);
            *(float4*)&s_kf[n * 68 + k] = g;
        }
        s_kf[(t4 >> 1) * 68 + 64 + (t4 & 1)] = 0.f;
    }
    __syncthreads();   // kf, q, wv visible CTA-wide

    // ======================= PHASE B (warp-specialized) =======================
    if (wid < 4) {
        // ---- key GEMM: a-frags from g_wkA (coalesced LDG.128) ----
        const int mt = wid & 1;
        const int m0 = mt * 16;
        const int nb = (wid >> 1) * 8;
        const float* wk = g_wkA + (size_t)h * 2048;
        float acc[4][4] = {};
        #pragma unroll
        for (int k8 = 0; k8 < 8; k8++) {
            const int k0 = k8 * 8;
            float4 w = *(const float4*)&wk[(k8 * 2 + mt) * 128 + lane * 4];
            uint32_t a[4] = { __float_as_uint(w.x), __float_as_uint(w.y),
                              __float_as_uint(w.z), __float_as_uint(w.w) };
            #pragma unroll
            for (int t = 0; t < 4; t++) {
                const int nn = nb + t * 16;
                uint32_t bfr[2];
                bfr[0] = __float_as_uint(tf32r(s_kf[(nn + lr) * 68 + k0 + lc]));
                bfr[1] = __float_as_uint(tf32r(s_kf[(nn + lr) * 68 + k0 + lc + 4]));
                mma16n8k8(acc[t], a, bfr);
            }
        }
        #pragma unroll
        for (int t = 0; t < 4; t++) {
            const int n = nb + t * 16 + lc * 2, d = m0 + lr;
            s_keyT[n * 36 + d]           = tf32r(acc[t][0]);
            s_keyT[(n + 1) * 36 + d]     = tf32r(acc[t][1]);
            s_keyT[n * 36 + d + 8]       = tf32r(acc[t][2]);
            s_keyT[(n + 1) * 36 + d + 8] = tf32r(acc[t][3]);
        }
    } else {
        // ---- conv (128 threads): n = t4>>1, p0 = (t4&1)*32 ----
        const int t4 = tid - 128;
        const int n = t4 >> 1, p0 = (t4 & 1) * 32;
        const float* kr = s_kf + n * 68;
        float w0[4], w1[4], w2[4], w3[4];
        #pragma unroll
        for (int d = 0; d < 4; d++) {
            w0[d] = s_wv[d * 3]; w1[d] = s_wv[d * 3 + 1];
            w2[d] = s_wv[d * 3 + 2]; w3[d] = s_wv[12 + d];
        }
        float x0 = kr[p0], x1 = kr[p0 + 1];
        #pragma unroll
        for (int i = 0; i < 32; i++) {
            float x2 = kr[p0 + i + 2];
            float acc = x0;
            #pragma unroll
            for (int d = 0; d < 4; d++)
                acc += fmaxf(x0 * w0[d] + x1 * w1[d] + x2 * w2[d], 0.f) * w3[d];
            s_vT[(p0 + i) * 68 + n] = tf32r(acc);
            x0 = x1; x1 = x2;
        }
    }
    __syncthreads();

    const int m0 = (wid >> 1) * 16;       // q tile
    const int nb4 = (wid & 1) * 4;        // 4 n-tiles

    // ---- P3: S[q][n] = sum_d q[q][d] * keyT[n][d] -> S overlay (kf dead) ----
    {
        float acc[4][4] = {};
        #pragma unroll
        for (int k8 = 0; k8 < 4; k8++) {
            const int k0 = k8 * 8;
            uint32_t a[4];
            a[0] = __float_as_uint(s_q[(m0 + lr)     * 36 + k0 + lc]);
            a[1] = __float_as_uint(s_q[(m0 + lr + 8) * 36 + k0 + lc]);
            a[2] = __float_as_uint(s_q[(m0 + lr)     * 36 + k0 + lc + 4]);
            a[3] = __float_as_uint(s_q[(m0 + lr + 8) * 36 + k0 + lc + 4]);
            #pragma unroll
            for (int j = 0; j < 4; j++) {
                const int nn = (nb4 + j) * 8;
                uint32_t bfr[2];
                bfr[0] = __float_as_uint(s_keyT[(nn + lr) * 36 + k0 + lc]);
                bfr[1] = __float_as_uint(s_keyT[(nn + lr) * 36 + k0 + lc + 4]);
                mma16n8k8(acc[j], a, bfr);
            }
        }
        #pragma unroll
        for (int j = 0; j < 4; j++) {
            const int col = (nb4 + j) * 8 + lc * 2;
            *(float2*)&s_S[(m0 + lr)     * 68 + col] = make_float2(acc[j][0], acc[j][1]);
            *(float2*)&s_S[(m0 + lr + 8) * 68 + col] = make_float2(acc[j][2], acc[j][3]);
        }
    }
    __syncthreads();

    // ---- P4: softmax rows of S; global attn fp32, smem tf32 ----
    {
        const int r = tid >> 2, s3 = tid & 3;
        float* row = s_S + r * 68 + s3 * 16;
        float4 v0 = *(float4*)&row[0], v1 = *(float4*)&row[4];
        float4 v2 = *(float4*)&row[8], v3 = *(float4*)&row[12];
        float mx = fmaxf(fmaxf(fmaxf(v0.x, v0.y), fmaxf(v0.z, v0.w)),
                         fmaxf(fmaxf(v1.x, v1.y), fmaxf(v1.z, v1.w)));
        mx = fmaxf(mx, fmaxf(fmaxf(fmaxf(v2.x, v2.y), fmaxf(v2.z, v2.w)),
                             fmaxf(fmaxf(v3.x, v3.y), fmaxf(v3.z, v3.w))));
        mx = fmaxf(mx, __shfl_xor_sync(~0u, mx, 1));
        mx = fmaxf(mx, __shfl_xor_sync(~0u, mx, 2));
        float e[16];
        e[0]=__expf(v0.x-mx); e[1]=__expf(v0.y-mx); e[2]=__expf(v0.z-mx); e[3]=__expf(v0.w-mx);
        e[4]=__expf(v1.x-mx); e[5]=__expf(v1.y-mx); e[6]=__expf(v1.z-mx); e[7]=__expf(v1.w-mx);
        e[8]=__expf(v2.x-mx); e[9]=__expf(v2.y-mx); e[10]=__expf(v2.z-mx); e[11]=__expf(v2.w-mx);
        e[12]=__expf(v3.x-mx); e[13]=__expf(v3.y-mx); e[14]=__expf(v3.z-mx); e[15]=__expf(v3.w-mx);
        float ssum = 0.f;
        #pragma unroll
        for (int i = 0; i < 16; i++) ssum += e[i];
        ssum += __shfl_xor_sync(~0u, ssum, 1);
        ssum += __shfl_xor_sync(~0u, ssum, 2);
        const float inv = 1.f / ssum;
        float* gattn = attn_out + (((size_t)(b * Hc + h) * Nc + r) * Nc) + s3 * 16;
        #pragma unroll
        for (int u = 0; u < 4; u++) {
            float p0 = e[4*u] * inv, p1 = e[4*u+1] * inv,
                  p2 = e[4*u+2] * inv, p3 = e[4*u+3] * inv;
            *(float4*)&gattn[4 * u] = make_float4(p0, p1, p2, p3);
            *(float4*)&row[4 * u]   = make_float4(tf32r(p0), tf32r(p1), tf32r(p2), tf32r(p3));
        }
    }
    __syncthreads();

    // ---- P5: hout[q][p] = sum_n attn[q][n] * vT[p][n] (registers) ----
    float hacc[4][4] = {};
    {
        #pragma unroll
        for (int k8 = 0; k8 < 8; k8++) {
            const int k0 = k8 * 8;
            uint32_t a[4];
            a[0] = __float_as_uint(s_S[(m0 + lr)     * 68 + k0 + lc]);
            a[1] = __float_as_uint(s_S[(m0 + lr + 8) * 68 + k0 + lc]);
            a[2] = __float_as_uint(s_S[(m0 + lr)     * 68 + k0 + lc + 4]);
            a[3] = __float_as_uint(s_S[(m0 + lr + 8) * 68 + k0 + lc + 4]);
            #pragma unroll
            for (int j = 0; j < 4; j++) {
                const int pp = (nb4 + j) * 8;
                uint32_t bfr[2];
                bfr[0] = __float_as_uint(s_vT[(pp + lr) * 68 + k0 + lc]);
                bfr[1] = __float_as_uint(s_vT[(pp + lr) * 68 + k0 + lc + 4]);
                mma16n8k8(hacc[j], a, bfr);
            }
        }
    }
    __syncthreads();   // all P5 reads of S done -> hout overlay safe

    // ---- store hout (tf32) into S region ----
    {
        #pragma unroll
        for (int j = 0; j < 4; j++) {
            const int p = (nb4 + j) * 8 + lc * 2;
            *(float2*)&s_S[(m0 + lr) * 68 + p] =
                make_float2(tf32r(hacc[j][0]), tf32r(hacc[j][1]));
            *(float2*)&s_S[(m0 + lr + 8) * 68 + p] =
                make_float2(tf32r(hacc[j][2]), tf32r(hacc[j][3]));
        }
    }
    __syncthreads();

    // ---- P6: FC partial; b-frags from g_wfcB (coalesced LDG.64); REDG ----
    {
        const int fm = (wid >> 1) * 16;      // n rows
        const int fob = (wid & 1) * 4;       // o-tile base (4 of 8)
        const float* wf = g_wfcB + (size_t)h * 4096;
        float acc[4][4] = {};
        #pragma unroll
        for (int k8 = 0; k8 < 8; k8++) {
            const int k0 = k8 * 8;
            uint32_t a[4];
            a[0] = __float_as_uint(s_S[(fm + lr)     * 68 + k0 + lc]);
            a[1] = __float_as_uint(s_S[(fm + lr + 8) * 68 + k0 + lc]);
            a[2] = __float_as_uint(s_S[(fm + lr)     * 68 + k0 + lc + 4]);
            a[3] = __float_as_uint(s_S[(fm + lr + 8) * 68 + k0 + lc + 4]);
            #pragma unroll
            for (int t = 0; t < 4; t++) {
                float2 w = *(const float2*)&wf[(k8 * 8 + fob + t) * 64 + lane * 2];
                uint32_t bfr[2] = { __float_as_uint(w.x), __float_as_uint(w.y) };
                mma16n8k8(acc[t], a, bfr);
            }
        }
        float* ob = out + (size_t)b * 4096;
        #pragma unroll
        for (int t = 0; t < 4; t++) {
            const int o = (fob + t) * 8 + lc * 2;
            redg_add(ob + (fm + lr) * 64 + o,     acc[t][0]);
            redg_add(ob + (fm + lr) * 64 + o + 1, acc[t][1]);
            redg_add(ob + (fm + lr + 8) * 64 + o,     acc[t][2]);
            redg_add(ob + (fm + lr + 8) * 64 + o + 1, acc[t][3]);
        }
    }
}

// ---------------------------------------------------------------------------
extern "C" void kernel_launch(void* const* d_in, const int* in_sizes, int n_in,
                              void* d_out, int out_size) {
    const float* feat  = (const float*)d_in[0];
    const int*   sidx  = (const int*)  d_in[1];
    const float* gamma = (const float*)d_in[2];
    const float* beta  = (const float*)d_in[3];
    const float* Wq    = (const float*)d_in[4];
    const float* Wk    = (const float*)d_in[5];
    const float* Wv1   = (const float*)d_in[6];
    const float* Wv2   = (const float*)d_in[7];
    const float* Wfc   = (const float*)d_in[8];

    float* out  = (float*)d_out;
    float* attn = out + (size_t)Bc * Nc * 64;

    cudaFuncSetAttribute(ln_y_kernel, cudaFuncAttributeMaxDynamicSharedMemorySize, SMEMY);
    cudaFuncSetAttribute(head_mma,    cudaFuncAttributeMaxDynamicSharedMemorySize, SMEM2);

    ln_y_kernel<<<Bc, 256, SMEMY>>>(feat, gamma, beta, Wq, Wk, Wfc, out);
    head_mma<<<dim3(Bc, Hc), 256, SMEM2>>>(feat, sidx, Wv1, Wv2, out, attn);
}

// round 16
// speedup vs baseline: 1.8536x; 1.0956x over previous
#include <cuda_runtime.h>
#include <math.h>
#include <stdint.h>

#define Bc 512
#define Mc 4096
#define Nc 64
#define Hc 8

// Scratch (device globals, allocation-free rule)
__device__ float g_y[(size_t)Bc * Mc];       // 8 MB, LN'd feats, q-GEMM FRAGMENT ORDER
__device__ float g_wqB[Hc * 8 * 4 * 64];     // q-GEMM B frags  [h][k8][t4][lane*2]
__device__ float g_wkA[Hc * 8 * 2 * 128];    // key-GEMM A frags [h][k8][mt2][lane*4]
__device__ float g_wfcB[Hc * 8 * 8 * 64];    // FC B frags      [h][k8][ot8][lane*2]

__device__ __forceinline__ float tf32r(float x) {
    float r; asm("cvt.rna.tf32.f32 %0, %1;" : "=f"(r) : "f"(x)); return r;
}
__device__ __forceinline__ void mma16n8k8(float* c, const uint32_t* a, const uint32_t* b) {
    asm volatile(
        "mma.sync.aligned.m16n8k8.row.col.f32.tf32.tf32.f32 "
        "{%0,%1,%2,%3}, {%4,%5,%6,%7}, {%8,%9}, {%0,%1,%2,%3};"
        : "+f"(c[0]), "+f"(c[1]), "+f"(c[2]), "+f"(c[3])
        : "r"(a[0]), "r"(a[1]), "r"(a[2]), "r"(a[3]), "r"(b[0]), "r"(b[1]));
}
__device__ __forceinline__ uint32_t smem_u32(const void* p) {
    uint32_t a;
    asm("{ .reg .u64 t; cvta.to.shared.u64 t, %1; cvt.u32.u64 %0, t; }" : "=r"(a) : "l"(p));
    return a;
}
__device__ __forceinline__ void cp16(uint32_t s, const void* g) {
    asm volatile("cp.async.cg.shared.global [%0], [%1], 16;" :: "r"(s), "l"(g));
}
__device__ __forceinline__ void redg_add2(float* g, float a, float b) {
    asm volatile("red.global.add.v2.f32 [%0], {%1, %2};" :: "l"(g), "f"(a), "f"(b) : "memory");
}
#define CP_COMMIT()  asm volatile("cp.async.commit_group;" ::: "memory")
#define CP_WAIT(n)   asm volatile("cp.async.wait_group %0;" :: "n"(n) : "memory")
#define BAR_SYNC(id, cnt) asm volatile("bar.sync %0, %1;" :: "r"(id), "r"(cnt) : "memory")

// ---------------------------------------------------------------------------
// Kernel 0: LayerNorm -> g_y (tf32, affine, FRAGMENT-PACKED), zero out[b] row,
// AND (blocks 0..7) pack weights for head h = blockIdx.x. grid=B.
// ---------------------------------------------------------------------------
static constexpr int SMEMY = 4096 * 4 + 80;

__global__ __launch_bounds__(256) void ln_y_kernel(
    const float* __restrict__ feat, const float* __restrict__ gamma,
    const float* __restrict__ beta, const float* __restrict__ Wq,
    const float* __restrict__ Wk, const float* __restrict__ Wfc,
    float* __restrict__ out)
{
    extern __shared__ float sm[];
    float* s_x = sm;
    float* s_red = sm + 4096;

    const int b = blockIdx.x, tid = threadIdx.x;
    const int wid = tid >> 5, lane = tid & 31;
    const float4* x4 = (const float4*)(feat + (size_t)b * Mc);

    {   // zero this batch's out row (head REDG-accumulates into it)
        float4* o4 = (float4*)(out + (size_t)b * 4096);
        #pragma unroll
        for (int j = 0; j < 4; j++)
            o4[tid + j * 256] = make_float4(0.f, 0.f, 0.f, 0.f);
    }

    float sum = 0.f, sq = 0.f;
    for (int i = tid; i < 1024; i += 256) {
        float4 v = x4[i];
        *(float4*)&s_x[i * 4] = v;
        sum += v.x + v.y + v.z + v.w;
        sq  += v.x*v.x + v.y*v.y + v.z*v.z + v.w*v.w;
    }
    #pragma unroll
    for (int o = 16; o; o >>= 1) {
        sum += __shfl_xor_sync(~0u, sum, o);
        sq  += __shfl_xor_sync(~0u, sq,  o);
    }
    if (lane == 0) { s_red[wid] = sum; s_red[wid + 8] = sq; }
    __syncthreads();
    if (tid == 0) {
        float S = 0.f, Q = 0.f;
        #pragma unroll
        for (int i = 0; i < 8; i++) { S += s_red[i]; Q += s_red[i + 8]; }
        float mu = S * (1.f / Mc);
        s_red[16] = mu;
        s_red[17] = rsqrtf(Q * (1.f / Mc) - mu * mu + 1e-5f);
    }
    __syncthreads();
    const float mu = s_red[16], rstd = s_red[17];
    const float4* g4 = (const float4*)gamma;
    const float4* b4 = (const float4*)beta;
    for (int i = tid; i < 1024; i += 256) {
        float4 v = *(float4*)&s_x[i * 4];
        float4 g = g4[i], bb = b4[i];
        v.x = tf32r((v.x - mu) * rstd * g.x + bb.x);
        v.y = tf32r((v.y - mu) * rstd * g.y + bb.y);
        v.z = tf32r((v.z - mu) * rstd * g.z + bb.z);
        v.w = tf32r((v.w - mu) * rstd * g.w + bb.w);
        *(float4*)&s_x[i * 4] = v;
    }
    __syncthreads();
    // packed fragment write: i = (k8*4 + t)*32 + lane2 ; 4 values per lane
    for (int i = tid; i < 1024; i += 256) {
        int lane2 = i & 31, t = (i >> 5) & 3, k8 = i >> 7;
        int plr = lane2 >> 2, plc = lane2 & 3;
        int row = t * 16 + plr, col = k8 * 8 + plc;
        float4 v;
        v.x = s_x[row * 64 + col];
        v.y = s_x[(row + 8) * 64 + col];
        v.z = s_x[row * 64 + col + 4];
        v.w = s_x[(row + 8) * 64 + col + 4];
        *(float4*)&g_y[(size_t)b * 4096 + i * 4] = v;
    }

    // ---- blocks 0..7: pack weights for head h = b ----
    if (b < Hc) {
        const int h = b;
        for (int i = tid; i < 1024; i += 256) {
            int k8 = i >> 7, t = (i >> 5) & 3, ln2 = i & 31;
            int plr = ln2 >> 2, plc = ln2 & 3;
            const float* src = Wq + (size_t)(h * 32 + t * 8 + plr) * 64 + k8 * 8 + plc;
            *(float2*)&g_wqB[(size_t)h * 2048 + i * 2] =
                make_float2(tf32r(src[0]), tf32r(src[4]));
        }
        for (int i = tid; i < 512; i += 256) {
            int k8 = i >> 6, mt = (i >> 5) & 1, ln2 = i & 31;
            int plr = ln2 >> 2, plc = ln2 & 3;
            const float* src = Wk + (size_t)h * 2048 + (mt * 16 + plr) * 64 + k8 * 8 + plc;
            *(float4*)&g_wkA[(size_t)h * 2048 + i * 4] =
                make_float4(tf32r(src[0]), tf32r(src[8 * 64]),
                            tf32r(src[4]), tf32r(src[8 * 64 + 4]));
        }
        for (int i = tid; i < 2048; i += 256) {
            int k8 = i >> 8, ot = (i >> 5) & 7, ln2 = i & 31;
            int plr = ln2 >> 2, plc = ln2 & 3;
            const float* src = Wfc + (size_t)(ot * 8 + plr) * 512 + h * 64 + k8 * 8 + plc;
            *(float2*)&g_wfcB[(size_t)h * 4096 + i * 2] =
                make_float2(tf32r(src[0]), tf32r(src[4]));
        }
    }
}

// ---------------------------------------------------------------------------
// Kernel 1: per-(b,h) head. out_partial = attn @ (v @ Wfc_h^T)  (associativity:
// G = v@Wfc^T computed early; no hout roundtrip). smem:
//   @0     kf[64][68]  — gathered feats; S overlay (phase C+)
//   @4352  feat[4096]  — raw feats; v[64][68] natural-layout overlay in phase B
//   @8704  keyT[64][36] + q[64][36]@11008 — after C: G^T[64][68] overlay @8704
//   @13312 wv[16]
// total 13328 floats = 53.3 KB -> 4 CTA/SM.
// ---------------------------------------------------------------------------
static constexpr int SMEM2 = 13328 * 4;

__global__ __launch_bounds__(256, 4) void head_mma(
    const float* __restrict__ feat, const int* __restrict__ sidx,
    const float* __restrict__ Wv1, const float* __restrict__ Wv2,
    float* __restrict__ out, float* __restrict__ attn_out)
{
    extern __shared__ float sm[];
    float* s_kf   = sm;            // [64][68]
    float* s_S    = sm;            // overlay
    float* s_v    = sm + 4352;     // [n][p] pitch 68 (natural)
    float* s_feat = sm + 4352;
    float* s_keyT = sm + 8704;     // [n][d] pitch 36
    float* s_q    = sm + 11008;    // [q][d] pitch 36
    float* s_G    = sm + 8704;     // G^T [o][n] pitch 68 (after C)
    float* s_wv   = sm + 13312;    // wv1[12], wv2[4]

    const int b = blockIdx.x, h = blockIdx.y, tid = threadIdx.x;
    const int wid = tid >> 5, lane = tid & 31;
    const int lr = lane >> 2, lc = lane & 3;
    const int* idx = sidx + (size_t)h * Mc;
    const uint32_t sbase = smem_u32(sm);

    // ======================= PHASE A (warp-specialized) =======================
    if (wid < 4) {
        // ---- q GEMM entirely from global packed frags (no staging, no wait) ----
        const float* yb = g_y + (size_t)b * 4096;     // fragment-packed
        const float* wq = g_wqB + (size_t)h * 2048;
        float qacc[4][4] = {};
        #pragma unroll
        for (int k8 = 0; k8 < 8; k8++) {
            float4 av = *(const float4*)&yb[(k8 * 4 + wid) * 128 + lane * 4];
            uint32_t a[4] = { __float_as_uint(av.x), __float_as_uint(av.y),
                              __float_as_uint(av.z), __float_as_uint(av.w) };
            #pragma unroll
            for (int t = 0; t < 4; t++) {
                float2 w = *(const float2*)&wq[(k8 * 4 + t) * 64 + lane * 2];
                uint32_t bfr[2] = { __float_as_uint(w.x), __float_as_uint(w.y) };
                mma16n8k8(qacc[t], a, bfr);
            }
        }
        const int qm = wid * 16;
        #pragma unroll
        for (int t = 0; t < 4; t++) {
            const int d = t * 8 + lc * 2;
            s_q[(qm + lr) * 36 + d]         = tf32r(qacc[t][0] * 0.015625f);
            s_q[(qm + lr) * 36 + d + 1]     = tf32r(qacc[t][1] * 0.015625f);
            s_q[(qm + lr + 8) * 36 + d]     = tf32r(qacc[t][2] * 0.015625f);
            s_q[(qm + lr + 8) * 36 + d + 1] = tf32r(qacc[t][3] * 0.015625f);
        }
    } else {
        const int t4 = tid - 128;                // 0..127
        const float* xg = feat + (size_t)b * Mc;
        #pragma unroll
        for (int j = 0; j < 8; j++) {
            int i = t4 + j * 128;
            cp16(sbase + (uint32_t)(4352 + i * 4) * 4, xg + i * 4);
        }
        CP_COMMIT();
        if (t4 < 12) s_wv[t4] = Wv1[h * 12 + t4];
        if (t4 >= 32 && t4 < 36) s_wv[12 + t4 - 32] = Wv2[h * 4 + t4 - 32];
        CP_WAIT(0);
        BAR_SYNC(2, 128);

        // ---- gather kf from smem feat; zero conv pad ----
        const int4* idx4 = (const int4*)idx;
        #pragma unroll
        for (int j = 0; j < 8; j++) {
            int i = t4 + j * 128;                // 0..1023
            int4 v = idx4[i];
            int n = i >> 4, k = (i & 15) * 4;
            float4 g = make_float4(s_feat[v.x], s_feat[v.y], s_feat[v.z], s_feat[v.w]);
            *(float4*)&s_kf[n * 68 + k] = g;
        }
        s_kf[(t4 >> 1) * 68 + 64 + (t4 & 1)] = 0.f;
    }
    __syncthreads();   // kf, q, wv visible CTA-wide

    // ======================= PHASE B (warp-specialized) =======================
    if (wid < 4) {
        // ---- key GEMM: a-frags from g_wkA (coalesced LDG.128) ----
        const int mt = wid & 1;
        const int m0b = mt * 16;
        const int nb = (wid >> 1) * 8;
        const float* wk = g_wkA + (size_t)h * 2048;
        float acc[4][4] = {};
        #pragma unroll
        for (int k8 = 0; k8 < 8; k8++) {
            const int k0 = k8 * 8;
            float4 w = *(const float4*)&wk[(k8 * 2 + mt) * 128 + lane * 4];
            uint32_t a[4] = { __float_as_uint(w.x), __float_as_uint(w.y),
                              __float_as_uint(w.z), __float_as_uint(w.w) };
            #pragma unroll
            for (int t = 0; t < 4; t++) {
                const int nn = nb + t * 16;
                uint32_t bfr[2];
                bfr[0] = __float_as_uint(tf32r(s_kf[(nn + lr) * 68 + k0 + lc]));
                bfr[1] = __float_as_uint(tf32r(s_kf[(nn + lr) * 68 + k0 + lc + 4]));
                mma16n8k8(acc[t], a, bfr);
            }
        }
        #pragma unroll
        for (int t = 0; t < 4; t++) {
            const int n = nb + t * 16 + lc * 2, d = m0b + lr;
            s_keyT[n * 36 + d]           = tf32r(acc[t][0]);
            s_keyT[(n + 1) * 36 + d]     = tf32r(acc[t][1]);
            s_keyT[n * 36 + d + 8]       = tf32r(acc[t][2]);
            s_keyT[(n + 1) * 36 + d + 8] = tf32r(acc[t][3]);
        }
    } else {
        // ---- conv (128 threads): n = t4>>1, p0 = (t4&1)*32; v NATURAL layout ----
        const int t4 = tid - 128;
        const int n = t4 >> 1, p0 = (t4 & 1) * 32;
        const float* kr = s_kf + n * 68;
        float w0[4], w1[4], w2[4], w3[4];
        #pragma unroll
        for (int d = 0; d < 4; d++) {
            w0[d] = s_wv[d * 3]; w1[d] = s_wv[d * 3 + 1];
            w2[d] = s_wv[d * 3 + 2]; w3[d] = s_wv[12 + d];
        }
        float r[32];
        float x0 = kr[p0], x1 = kr[p0 + 1];
        #pragma unroll
        for (int i = 0; i < 32; i++) {
            float x2 = kr[p0 + i + 2];
            float acc = x0;
            #pragma unroll
            for (int d = 0; d < 4; d++)
                acc += fmaxf(x0 * w0[d] + x1 * w1[d] + x2 * w2[d], 0.f) * w3[d];
            r[i] = tf32r(acc);
            x0 = x1; x1 = x2;
        }
        #pragma unroll
        for (int j = 0; j < 8; j++)
            *(float4*)&s_v[n * 68 + p0 + j * 4] =
                make_float4(r[4*j], r[4*j+1], r[4*j+2], r[4*j+3]);
    }
    __syncthreads();

    const int m0 = (wid >> 1) * 16;       // q / n tile
    const int nb4 = (wid & 1) * 4;        // 4 n- / o- tiles

    // ====== PHASE C: S = q@keyT^T (store to kf region); G = v@wfc^T ======
    {
        float acc[4][4] = {};
        #pragma unroll
        for (int k8 = 0; k8 < 4; k8++) {
            const int k0 = k8 * 8;
            uint32_t a[4];
            a[0] = __float_as_uint(s_q[(m0 + lr)     * 36 + k0 + lc]);
            a[1] = __float_as_uint(s_q[(m0 + lr + 8) * 36 + k0 + lc]);
            a[2] = __float_as_uint(s_q[(m0 + lr)     * 36 + k0 + lc + 4]);
            a[3] = __float_as_uint(s_q[(m0 + lr + 8) * 36 + k0 + lc + 4]);
            #pragma unroll
            for (int j = 0; j < 4; j++) {
                const int nn = (nb4 + j) * 8;
                uint32_t bfr[2];
                bfr[0] = __float_as_uint(s_keyT[(nn + lr) * 36 + k0 + lc]);
                bfr[1] = __float_as_uint(s_keyT[(nn + lr) * 36 + k0 + lc + 4]);
                mma16n8k8(acc[j], a, bfr);
            }
        }
        #pragma unroll
        for (int j = 0; j < 4; j++) {
            const int col = (nb4 + j) * 8 + lc * 2;
            *(float2*)&s_S[(m0 + lr)     * 68 + col] = make_float2(acc[j][0], acc[j][1]);
            *(float2*)&s_S[(m0 + lr + 8) * 68 + col] = make_float2(acc[j][2], acc[j][3]);
        }
    }
    float gacc[4][4] = {};
    {
        const float* wf = g_wfcB + (size_t)h * 4096;
        #pragma unroll
        for (int k8 = 0; k8 < 8; k8++) {
            const int k0 = k8 * 8;
            uint32_t a[4];
            a[0] = __float_as_uint(s_v[(m0 + lr)     * 68 + k0 + lc]);
            a[1] = __float_as_uint(s_v[(m0 + lr + 8) * 68 + k0 + lc]);
            a[2] = __float_as_uint(s_v[(m0 + lr)     * 68 + k0 + lc + 4]);
            a[3] = __float_as_uint(s_v[(m0 + lr + 8) * 68 + k0 + lc + 4]);
            #pragma unroll
            for (int t = 0; t < 4; t++) {
                float2 w = *(const float2*)&wf[(k8 * 8 + nb4 + t) * 64 + lane * 2];
                uint32_t bfr[2] = { __float_as_uint(w.x), __float_as_uint(w.y) };
                mma16n8k8(gacc[t], a, bfr);
            }
        }
    }
    __syncthreads();   // keyT/q + v reads done -> G^T overlay safe; S visible

    // ---- store G^T[o][n] (tf32) into keyT/q region ----
    {
        #pragma unroll
        for (int j = 0; j < 4; j++) {
            const int o = (nb4 + j) * 8 + lc * 2;
            s_G[o * 68 + m0 + lr]           = tf32r(gacc[j][0]);
            s_G[(o + 1) * 68 + m0 + lr]     = tf32r(gacc[j][1]);
            s_G[o * 68 + m0 + lr + 8]       = tf32r(gacc[j][2]);
            s_G[(o + 1) * 68 + m0 + lr + 8] = tf32r(gacc[j][3]);
        }
    }

    // ---- P4: softmax rows of S; global attn fp32, smem tf32 ----
    {
        const int r = tid >> 2, s3 = tid & 3;
        float* row = s_S + r * 68 + s3 * 16;
        float4 v0 = *(float4*)&row[0], v1 = *(float4*)&row[4];
        float4 v2 = *(float4*)&row[8], v3 = *(float4*)&row[12];
        float mx = fmaxf(fmaxf(fmaxf(v0.x, v0.y), fmaxf(v0.z, v0.w)),
                         fmaxf(fmaxf(v1.x, v1.y), fmaxf(v1.z, v1.w)));
        mx = fmaxf(mx, fmaxf(fmaxf(fmaxf(v2.x, v2.y), fmaxf(v2.z, v2.w)),
                             fmaxf(fmaxf(v3.x, v3.y), fmaxf(v3.z, v3.w))));
        mx = fmaxf(mx, __shfl_xor_sync(~0u, mx, 1));
        mx = fmaxf(mx, __shfl_xor_sync(~0u, mx, 2));
        float e[16];
        e[0]=__expf(v0.x-mx); e[1]=__expf(v0.y-mx); e[2]=__expf(v0.z-mx); e[3]=__expf(v0.w-mx);
        e[4]=__expf(v1.x-mx); e[5]=__expf(v1.y-mx); e[6]=__expf(v1.z-mx); e[7]=__expf(v1.w-mx);
        e[8]=__expf(v2.x-mx); e[9]=__expf(v2.y-mx); e[10]=__expf(v2.z-mx); e[11]=__expf(v2.w-mx);
        e[12]=__expf(v3.x-mx); e[13]=__expf(v3.y-mx); e[14]=__expf(v3.z-mx); e[15]=__expf(v3.w-mx);
        float ssum = 0.f;
        #pragma unroll
        for (int i = 0; i < 16; i++) ssum += e[i];
        ssum += __shfl_xor_sync(~0u, ssum, 1);
        ssum += __shfl_xor_sync(~0u, ssum, 2);
        const float inv = 1.f / ssum;
        float* gattn = attn_out + (((size_t)(b * Hc + h) * Nc + r) * Nc) + s3 * 16;
        #pragma unroll
        for (int u = 0; u < 4; u++) {
            float p0 = e[4*u] * inv, p1 = e[4*u+1] * inv,
                  p2 = e[4*u+2] * inv, p3 = e[4*u+3] * inv;
            *(float4*)&gattn[4 * u] = make_float4(p0, p1, p2, p3);
            *(float4*)&row[4 * u]   = make_float4(tf32r(p0), tf32r(p1), tf32r(p2), tf32r(p3));
        }
    }
    __syncthreads();   // S(attn) + G^T visible

    // ---- P5': out[q][o] = sum_n attn[q][n] * G[n][o]; red.v2 accumulate ----
    {
        float acc[4][4] = {};
        #pragma unroll
        for (int k8 = 0; k8 < 8; k8++) {
            const int k0 = k8 * 8;
            uint32_t a[4];
            a[0] = __float_as_uint(s_S[(m0 + lr)     * 68 + k0 + lc]);
            a[1] = __float_as_uint(s_S[(m0 + lr + 8) * 68 + k0 + lc]);
            a[2] = __float_as_uint(s_S[(m0 + lr)     * 68 + k0 + lc + 4]);
            a[3] = __float_as_uint(s_S[(m0 + lr + 8) * 68 + k0 + lc + 4]);
            #pragma unroll
            for (int j = 0; j < 4; j++) {
                const int oo = (nb4 + j) * 8;
                uint32_t bfr[2];
                bfr[0] = __float_as_uint(s_G[(oo + lr) * 68 + k0 + lc]);
                bfr[1] = __float_as_uint(s_G[(oo + lr) * 68 + k0 + lc + 4]);
                mma16n8k8(acc[j], a, bfr);
            }
        }
        float* ob = out + (size_t)b * 4096;
        #pragma unroll
        for (int j = 0; j < 4; j++) {
            const int o = (nb4 + j) * 8 + lc * 2;
            redg_add2(ob + (m0 + lr) * 64 + o,     acc[j][0], acc[j][1]);
            redg_add2(ob + (m0 + lr + 8) * 64 + o, acc[j][2], acc[j][3]);
        }
    }
}

// ---------------------------------------------------------------------------
extern "C" void kernel_launch(void* const* d_in, const int* in_sizes, int n_in,
                              void* d_out, int out_size) {
    const float* feat  = (const float*)d_in[0];
    const int*   sidx  = (const int*)  d_in[1];
    const float* gamma = (const float*)d_in[2];
    const float* beta  = (const float*)d_in[3];
    const float* Wq    = (const float*)d_in[4];
    const float* Wk    = (const float*)d_in[5];
    const float* Wv1   = (const float*)d_in[6];
    const float* Wv2   = (const float*)d_in[7];
    const float* Wfc   = (const float*)d_in[8];

    float* out  = (float*)d_out;
    float* attn = out + (size_t)Bc * Nc * 64;

    cudaFuncSetAttribute(ln_y_kernel, cudaFuncAttributeMaxDynamicSharedMemorySize, SMEMY);
    cudaFuncSetAttribute(head_mma,    cudaFuncAttributeMaxDynamicSharedMemorySize, SMEM2);

    ln_y_kernel<<<Bc, 256, SMEMY>>>(feat, gamma, beta, Wq, Wk, Wfc, out);
    head_mma<<<dim3(Bc, Hc), 256, SMEM2>>>(feat, sidx, Wv1, Wv2, out, attn);
}